// round 10
// baseline (speedup 1.0000x reference)
#include <cuda_runtime.h>
#include <math.h>
#include <stdint.h>

constexpr int Bb = 32;
constexpr int Hh = 56;
constexpr int Ww = 56;
constexpr int Cc = 128;
constexpr int Nn = Hh * Ww;              // 3136
constexpr int Mm = Bb * Nn;              // 100352
constexpr size_t MC = (size_t)Mm * Cc;

__device__ float g_t0[MC];
__device__ float g_t1[MC];
__device__ float g_x1a[MC];
__device__ float g_x2a[MC];
__device__ float g_q[MC];
__device__ float g_k[MC];
__device__ float g_v[MC];
__device__ float g_att[MC];
__device__ float g_stats[2 * Mm];        // LN mean | rstd
__device__ float g_part[784 * 256];
__device__ float g_s1[Cc];
__device__ float g_h1[Cc];
__device__ float g_s2[Cc];
__device__ float g_h2[Cc];

__device__ __forceinline__ float tf32r(float x) {
    uint32_t u;
    asm("cvt.rna.tf32.f32 %0, %1;" : "=r"(u) : "f"(x));
    return __uint_as_float(u);
}

__device__ __forceinline__ void mma_tf32(float* c, const float4& a, const float2& b) {
    asm volatile(
        "mma.sync.aligned.m16n8k8.row.col.f32.tf32.tf32.f32 "
        "{%0,%1,%2,%3}, {%4,%5,%6,%7}, {%8,%9}, {%0,%1,%2,%3};"
        : "+f"(c[0]), "+f"(c[1]), "+f"(c[2]), "+f"(c[3])
        : "r"(__float_as_uint(a.x)), "r"(__float_as_uint(a.y)),
          "r"(__float_as_uint(a.z)), "r"(__float_as_uint(a.w)),
          "r"(__float_as_uint(b.x)), "r"(__float_as_uint(b.y)));
}

// ---------------------------------------------------------------------------
// Per-channel roll. MODE 0: H,+c  1: W,+c  2: W,-c
// ---------------------------------------------------------------------------
template <int MODE>
__launch_bounds__(256)
__global__ void roll_k(const float* __restrict__ in, float* __restrict__ out) {
    __shared__ float tile[56 * 128];
    const int tid = threadIdx.x;
    const int b = blockIdx.x / 56;
    const int f = blockIdx.x % 56;
    const size_t base   = (MODE == 0) ? ((size_t)b * Nn + f) * 128
                                      : ((size_t)(b * 56 + f) * 56) * 128;
    const int    stride = (MODE == 0) ? 56 * 128 : 128;

    #pragma unroll
    for (int e = tid; e < 56 * 32; e += 256) {
        int rowi = e >> 5, c4 = e & 31;
        ((float4*)tile)[rowi * 32 + c4] =
            *(const float4*)(in + base + (size_t)rowi * stride + c4 * 4);
    }
    __syncthreads();

    #pragma unroll
    for (int e = tid; e < 56 * 128; e += 256) {
        int pos = e >> 7, c = e & 127;
        int cm = c % 56;
        int src = (MODE == 2) ? pos + cm : pos - cm;
        if (src < 0) src += 56;
        if (src >= 56) src -= 56;
        out[base + (size_t)pos * stride + c] = tile[src * 128 + c];
    }
}

// ---------------------------------------------------------------------------
// TF32 GEMM, BM=64 / BN=128, 3 CTAs/SM. Warp tile 16x64 (8 warps: 4m x 2n).
// Coalesced LDG.128 -> XOR-swizzled single-buffer smem A (8KB); register
// prefetch distance 2; B resident fragment-order smem (64KB chunk of 128
// k-cols; K=256 swaps at s==4). Two barriers per slice (hidden by 24 warps).
// AMODE: 0 plain A[M,K]; 1 split+per-col affine on A1; 2 split+LN fold;
//        3 split+relu(bn1)*bn2 fold. QKV: grid.y selects B/bias/C.
// ---------------------------------------------------------------------------
enum { EPI_GELU = 0, EPI_BIAS = 1, EPI_RES = 2 };
constexpr int SM_ALL = 16 * 16 * 32 * 8 + 64 * 32 * 4;   // 64KB B + 8KB A = 72KB

template <int K, int EPI, int AMODE, bool BT, bool QKV>
__launch_bounds__(256, 3)
__global__ void gemm_k(const float* __restrict__ A0, const float* __restrict__ A1,
                       const float* __restrict__ B0, const float* __restrict__ B1,
                       const float* __restrict__ B2,
                       const float* __restrict__ bias0, const float* __restrict__ bias1,
                       const float* __restrict__ bias2,
                       const float* __restrict__ res,
                       const float* __restrict__ p0, const float* __restrict__ p1,
                       const float* __restrict__ p2, const float* __restrict__ p3,
                       float* __restrict__ C0, float* __restrict__ C1,
                       float* __restrict__ C2) {
    extern __shared__ float smem[];
    float2* Bs = (float2*)smem;                 // [16 k8][16 nt][32 lane]
    float*  As = smem + 16384;                  // 64 rows x 32 (swizzled)

    const float* Bm = B0;
    const float* bias = bias0;
    float* Cm = C0;
    if (QKV) {
        int y = blockIdx.y;
        if (y == 1) { Bm = B1; bias = bias1; Cm = C1; }
        else if (y == 2) { Bm = B2; bias = bias2; Cm = C2; }
    }

    const int tid  = threadIdx.x;
    const int lane = tid & 31;
    const int wid  = tid >> 5;
    const int wm   = wid & 3;          // 16-row block
    const int wn   = wid >> 2;         // 64-col block
    const int row0 = blockIdx.x * 64;
    const int lr   = lane >> 2;
    const int lc   = lane & 3;

    auto loadB = [&](int ko) {
        for (int frag = wid; frag < 256; frag += 8) {
            int k8l = frag >> 4, nt = frag & 15;
            int kk = ko + k8l * 8 + lc, n = nt * 8 + lr;
            float b0v, b1v;
            if (BT) { b0v = Bm[(size_t)n * K + kk];   b1v = Bm[(size_t)n * K + kk + 4]; }
            else    { b0v = Bm[(size_t)kk * 128 + n]; b1v = Bm[(size_t)(kk + 4) * 128 + n]; }
            Bs[frag * 32 + lane] = make_float2(tf32r(b0v), tf32r(b1v));
        }
    };

    // ---- A producer: thread loads rows (tid>>3)+{0,32}, c4 block tid&7 ----
    const int arow = tid >> 3;         // 0..31, + i*32
    const int ac4  = tid & 7;
    float mrow[2], rrow[2];
    if (AMODE == 2) {
        #pragma unroll
        for (int i = 0; i < 2; i++) {
            int gr = row0 + arow + i * 32;
            mrow[i] = p0[gr];
            rrow[i] = p1[gr];
        }
    }

    auto fetch4 = [&](int i, int c) -> float4 {
        int gr = row0 + arow + i * 32;
        float4 v;
        if (AMODE == 0) {
            v = *(const float4*)(A0 + (size_t)gr * K + c);
        } else {
            v = (c < 128) ? *(const float4*)(A0 + (size_t)gr * 128 + c)
                          : *(const float4*)(A1 + (size_t)gr * 128 + (c - 128));
            if (AMODE == 1) {
                if (c >= 128) {
                    float4 s = *(const float4*)(p0 + c - 128);
                    float4 h = *(const float4*)(p1 + c - 128);
                    v.x = v.x * s.x + h.x; v.y = v.y * s.y + h.y;
                    v.z = v.z * s.z + h.z; v.w = v.w * s.w + h.w;
                }
            } else if (AMODE == 2) {
                float4 g = *(const float4*)(p2 + c);
                float4 bb = *(const float4*)(p3 + c);
                float mn = mrow[i], rs = rrow[i];
                v.x = (v.x - mn) * rs * g.x + bb.x;
                v.y = (v.y - mn) * rs * g.y + bb.y;
                v.z = (v.z - mn) * rs * g.z + bb.z;
                v.w = (v.w - mn) * rs * g.w + bb.w;
            } else {            // AMODE 3: relu(bn1)*bn2 fold on A1
                if (c >= 128) {
                    float4 s1 = *(const float4*)(p0 + c - 128);
                    float4 h1 = *(const float4*)(p1 + c - 128);
                    float4 s2 = *(const float4*)(p2 + c - 128);
                    float4 h2 = *(const float4*)(p3 + c - 128);
                    v.x = fmaxf(v.x * s1.x + h1.x, 0.f) * s2.x + h2.x;
                    v.y = fmaxf(v.y * s1.y + h1.y, 0.f) * s2.y + h2.y;
                    v.z = fmaxf(v.z * s1.z + h1.z, 0.f) * s2.z + h2.z;
                    v.w = fmaxf(v.w * s1.w + h1.w, 0.f) * s2.w + h2.w;
                }
            }
        }
        return make_float4(tf32r(v.x), tf32r(v.y), tf32r(v.z), tf32r(v.w));
    };

    float4 pa[2][2];
    auto gather = [&](int kc, int set) {
        int c = kc + ac4 * 4;
        #pragma unroll
        for (int i = 0; i < 2; i++) pa[set][i] = fetch4(i, c);
    };

    loadB(0);
    gather(0, 0);
    gather(32, 1);

    float acc[8][4] = {};
    constexpr int NS = K / 32;

    #pragma unroll
    for (int s = 0; s < NS; s++) {
        if (s > 0) __syncthreads();            // mma(s-1) done everywhere
        if (K > 128 && s == 4) loadB(128);     // swap B chunk
        const int set = s & 1;
        #pragma unroll
        for (int i = 0; i < 2; i++) {
            int row = arow + i * 32;
            *(float4*)(As + row * 32 + 4 * (ac4 ^ (row & 7))) = pa[set][i];
        }
        __syncthreads();                        // A tile (and B swap) ready
        if (s + 2 < NS) gather((s + 2) * 32, set);
        const int kb = (s & 3) * 4;
        #pragma unroll
        for (int k8 = 0; k8 < 4; k8++) {
            int r = wm * 16 + lr;
            int s0 = 4 * ((2 * k8) ^ lr) + lc;
            int s1 = 4 * ((2 * k8 + 1) ^ lr) + lc;
            const float* b1p = As + r * 32;
            const float* b2p = As + (r + 8) * 32;
            float4 av = make_float4(b1p[s0], b2p[s0], b1p[s1], b2p[s1]);
            #pragma unroll
            for (int u = 0; u < 8; u++) {
                float2 b = Bs[((kb + k8) * 16 + wn * 8 + u) * 32 + lane];
                mma_tf32(acc[u], av, b);
            }
        }
    }

    const int ec = lc * 2;
    int m0 = row0 + wm * 16 + lr;
    #pragma unroll
    for (int u = 0; u < 8; u++) {
        int n = wn * 64 + u * 8 + ec;
        float b0 = bias[n], b1 = bias[n + 1];
        float v0 = acc[u][0] + b0;
        float v1 = acc[u][1] + b1;
        float v2 = acc[u][2] + b0;
        float v3 = acc[u][3] + b1;
        if (EPI == EPI_GELU) {
            v0 = 0.5f * v0 * (1.0f + erff(v0 * 0.70710678f));
            v1 = 0.5f * v1 * (1.0f + erff(v1 * 0.70710678f));
            v2 = 0.5f * v2 * (1.0f + erff(v2 * 0.70710678f));
            v3 = 0.5f * v3 * (1.0f + erff(v3 * 0.70710678f));
        } else if (EPI == EPI_RES) {
            float2 r0 = *(const float2*)(res + (size_t)m0 * 128 + n);
            float2 rr = *(const float2*)(res + (size_t)(m0 + 8) * 128 + n);
            v0 += r0.x; v1 += r0.y; v2 += rr.x; v3 += rr.y;
        }
        *(float2*)(Cm + (size_t)m0 * 128 + n)       = make_float2(v0, v1);
        *(float2*)(Cm + (size_t)(m0 + 8) * 128 + n) = make_float2(v2, v3);
    }
}

// ---------------------------------------------------------------------------
// LayerNorm stats only: per-token mean & rstd over the 256-wide concat
// ---------------------------------------------------------------------------
__global__ void ln_stats_k(const float* __restrict__ x1a, const float* __restrict__ x2a,
                           float* __restrict__ mean, float* __restrict__ rstd) {
    int warp = (blockIdx.x * blockDim.x + threadIdx.x) >> 5;
    int lane = threadIdx.x & 31;
    if (warp >= Mm) return;
    float s = 0.f, sq = 0.f;
    #pragma unroll
    for (int kq = 0; kq < 4; kq++) {
        float a = x1a[(size_t)warp * 128 + lane + 32 * kq];
        float b = x2a[(size_t)warp * 128 + lane + 32 * kq];
        s += a + b; sq += a * a + b * b;
    }
    #pragma unroll
    for (int o = 16; o > 0; o >>= 1) {
        s  += __shfl_xor_sync(0xffffffffu, s, o);
        sq += __shfl_xor_sync(0xffffffffu, sq, o);
    }
    if (lane == 0) {
        float mu = s * (1.f / 256.f);
        float var = sq * (1.f / 256.f) - mu * mu;
        mean[warp] = mu;
        rstd[warp] = rsqrtf(var + 1e-5f);
    }
}

// ---------------------------------------------------------------------------
// Window attention on tensor cores (validated in R5)
// ---------------------------------------------------------------------------
constexpr int QS_STRIDE = 132;
constexpr int VS_STRIDE = 136;
constexpr int PS_STRIDE = 68;
constexpr int ATTN_SMEM = (2 * 64 * QS_STRIDE + 64 * VS_STRIDE + 64 * PS_STRIDE) * 4;

__launch_bounds__(256)
__global__ void attn_k(const float* __restrict__ q, const float* __restrict__ k,
                       const float* __restrict__ v, float* __restrict__ out) {
    extern __shared__ float sm[];
    float* Qs = sm;
    float* Ks = Qs + 64 * QS_STRIDE;
    float* Vs = Ks + 64 * QS_STRIDE;
    float* Ps = Vs + 64 * VS_STRIDE;

    const int widx = blockIdx.x;
    const int b = widx >> 6, wh = (widx >> 3) & 7, ww = widx & 7;
    const int tid  = threadIdx.x;
    const int lane = tid & 31, w = tid >> 5;
    const int wm = w & 3, wn = w >> 2;
    const int lr = lane >> 2, lc = lane & 3;

    auto grow = [&](int i) -> size_t {
        return ((size_t)(b * Nn + (wh * 7 + i / 7) * 56 + ww * 7 + (i % 7))) * 128;
    };

    for (int e = tid; e < 49 * 32; e += 256) {
        int i = e >> 5, c4 = (e & 31) * 4;
        size_t g = grow(i) + c4;
        float4 a  = *(const float4*)(q + g);
        float4 kk = *(const float4*)(k + g);
        float4 vv = *(const float4*)(v + g);
        *(float4*)(Qs + i * QS_STRIDE + c4) =
            make_float4(tf32r(a.x), tf32r(a.y), tf32r(a.z), tf32r(a.w));
        *(float4*)(Ks + i * QS_STRIDE + c4) =
            make_float4(tf32r(kk.x), tf32r(kk.y), tf32r(kk.z), tf32r(kk.w));
        *(float4*)(Vs + i * VS_STRIDE + c4) =
            make_float4(tf32r(vv.x), tf32r(vv.y), tf32r(vv.z), tf32r(vv.w));
    }
    for (int e = tid; e < 15 * QS_STRIDE; e += 256) {
        Qs[49 * QS_STRIDE + e] = 0.f;
        Ks[49 * QS_STRIDE + e] = 0.f;
    }
    for (int e = tid; e < 15 * VS_STRIDE; e += 256) Vs[49 * VS_STRIDE + e] = 0.f;
    __syncthreads();

    float acc[4][4] = {};
    #pragma unroll
    for (int k8 = 0; k8 < 16; k8++) {
        int r = wm * 16 + lr, c = k8 * 8 + lc;
        float4 a = make_float4(Qs[r * QS_STRIDE + c],     Qs[(r + 8) * QS_STRIDE + c],
                               Qs[r * QS_STRIDE + c + 4], Qs[(r + 8) * QS_STRIDE + c + 4]);
        #pragma unroll
        for (int u = 0; u < 4; u++) {
            int n = wn * 32 + u * 8 + lr;
            float2 bf = make_float2(Ks[n * QS_STRIDE + c], Ks[n * QS_STRIDE + c + 4]);
            mma_tf32(acc[u], a, bf);
        }
    }
    #pragma unroll
    for (int u = 0; u < 4; u++) {
        int r = wm * 16 + lr, n = wn * 32 + u * 8 + lc * 2;
        *(float2*)(Ps + r * PS_STRIDE + n)       = make_float2(acc[u][0], acc[u][1]);
        *(float2*)(Ps + (r + 8) * PS_STRIDE + n) = make_float2(acc[u][2], acc[u][3]);
    }
    __syncthreads();

    if (tid < 49) {
        const float scale = 0.08838834764831845f;
        float* r = Ps + tid * PS_STRIDE;
        float mx = r[0];
        #pragma unroll 7
        for (int j = 1; j < 49; j++) mx = fmaxf(mx, r[j]);
        float s = 0.f;
        #pragma unroll 7
        for (int j = 0; j < 49; j++) { float e = expf((r[j] - mx) * scale); r[j] = e; s += e; }
        float inv = 1.f / s;
        #pragma unroll 7
        for (int j = 0; j < 49; j++) r[j] = tf32r(r[j] * inv);
        #pragma unroll
        for (int j = 49; j < 64; j++) r[j] = 0.f;
    }
    __syncthreads();

    float o[8][4] = {};
    #pragma unroll
    for (int k8 = 0; k8 < 8; k8++) {
        int r = wm * 16 + lr, c = k8 * 8 + lc;
        float4 a = make_float4(Ps[r * PS_STRIDE + c],     Ps[(r + 8) * PS_STRIDE + c],
                               Ps[r * PS_STRIDE + c + 4], Ps[(r + 8) * PS_STRIDE + c + 4]);
        #pragma unroll
        for (int u = 0; u < 8; u++) {
            int n = wn * 64 + u * 8 + lr;
            float2 bf = make_float2(Vs[c * VS_STRIDE + n], Vs[(c + 4) * VS_STRIDE + n]);
            mma_tf32(o[u], a, bf);
        }
    }
    int r0 = wm * 16 + lr;
    #pragma unroll
    for (int u = 0; u < 8; u++) {
        int n = wn * 64 + u * 8 + lc * 2;
        if (r0 < 49)     *(float2*)(out + grow(r0) + n)     = make_float2(o[u][0], o[u][1]);
        if (r0 + 8 < 49) *(float2*)(out + grow(r0 + 8) + n) = make_float2(o[u][2], o[u][3]);
    }
}

// ---------------------------------------------------------------------------
// BatchNorm pieces
// ---------------------------------------------------------------------------
__global__ void bn_stats_k(const float* __restrict__ x, float* __restrict__ part) {
    int c = threadIdx.x & 127;
    int half = threadIdx.x >> 7;
    float s = 0.f, sq = 0.f;
    int rbeg = blockIdx.x * 128 + half;
    int rend = blockIdx.x * 128 + 128;
    for (int r = rbeg; r < rend; r += 2) {
        float vv = x[(size_t)r * 128 + c];
        s += vv; sq += vv * vv;
    }
    __shared__ float sh[512];
    sh[threadIdx.x] = s;
    sh[256 + threadIdx.x] = sq;
    __syncthreads();
    if (half == 0) {
        part[blockIdx.x * 256 + c]       = sh[c] + sh[128 + c];
        part[blockIdx.x * 256 + 128 + c] = sh[256 + c] + sh[256 + 128 + c];
    }
}

// read-only: stats of relu(bn1(x))
__global__ void bn2_stats_k(const float* __restrict__ x,
                            const float* __restrict__ s1, const float* __restrict__ h1,
                            float* __restrict__ part) {
    int c = threadIdx.x & 127;
    int half = threadIdx.x >> 7;
    float sc = s1[c], sh_ = h1[c];
    float s = 0.f, sq = 0.f;
    int rbeg = blockIdx.x * 128 + half;
    int rend = blockIdx.x * 128 + 128;
    for (int r = rbeg; r < rend; r += 2) {
        float vv = fmaxf(x[(size_t)r * 128 + c] * sc + sh_, 0.f);
        s += vv; sq += vv * vv;
    }
    __shared__ float shm[512];
    shm[threadIdx.x] = s;
    shm[256 + threadIdx.x] = sq;
    __syncthreads();
    if (half == 0) {
        part[blockIdx.x * 256 + c]       = shm[c] + shm[128 + c];
        part[blockIdx.x * 256 + 128 + c] = shm[256 + c] + shm[256 + 128 + c];
    }
}

__global__ void bn_reduce_k(const float* __restrict__ part, const float* __restrict__ g,
                            const float* __restrict__ beta, float* __restrict__ scale,
                            float* __restrict__ shift) {
    int c = threadIdx.x;
    float s = 0.f, sq = 0.f;
    for (int i = 0; i < 784; i++) {
        s  += part[i * 256 + c];
        sq += part[i * 256 + 128 + c];
    }
    float mean = s / (float)Mm;
    float var  = sq / (float)Mm - mean * mean;
    float sc_  = g[c] * rsqrtf(var + 1e-5f);
    scale[c] = sc_;
    shift[c] = beta[c] - mean * sc_;
}

// ---------------------------------------------------------------------------
// Host launch
// ---------------------------------------------------------------------------
static float* symaddr(const void* devsym) {
    void* p = nullptr;
    cudaGetSymbolAddress(&p, devsym);
    return (float*)p;
}

extern "C" void kernel_launch(void* const* d_in, const int* in_sizes, int n_in,
                              void* d_out, int out_size) {
    const float* x     = (const float*)d_in[0];
    const float* fc1_w = (const float*)d_in[1];
    const float* fc1_b = (const float*)d_in[2];
    const float* fc2_w = (const float*)d_in[3];
    const float* fc2_b = (const float*)d_in[4];
    const float* fc3_w = (const float*)d_in[5];
    const float* fc3_b = (const float*)d_in[6];
    const float* fc4_w = (const float*)d_in[7];
    const float* fc4_b = (const float*)d_in[8];
    const float* fc5_w = (const float*)d_in[9];
    const float* fc5_b = (const float*)d_in[10];
    const float* fc6_w = (const float*)d_in[11];
    const float* fc6_b = (const float*)d_in[12];
    const float* ln_w  = (const float*)d_in[13];
    const float* ln_b  = (const float*)d_in[14];
    const float* q_w   = (const float*)d_in[15];
    const float* q_b   = (const float*)d_in[16];
    const float* k_w   = (const float*)d_in[17];
    const float* k_b   = (const float*)d_in[18];
    const float* v_w   = (const float*)d_in[19];
    const float* v_b   = (const float*)d_in[20];
    const float* bn1_g = (const float*)d_in[21];
    const float* bn1_b = (const float*)d_in[22];
    const float* bn2_g = (const float*)d_in[23];
    const float* bn2_b = (const float*)d_in[24];

    float* t0   = symaddr(g_t0);
    float* t1   = symaddr(g_t1);
    float* x1a  = symaddr(g_x1a);
    float* x2a  = symaddr(g_x2a);
    float* qb   = symaddr(g_q);
    float* kb   = symaddr(g_k);
    float* vb   = symaddr(g_v);
    float* att  = symaddr(g_att);
    float* stat = symaddr(g_stats);
    float* mean = stat;
    float* rstd = stat + Mm;
    float* part = symaddr(g_part);
    float* s1   = symaddr(g_s1);
    float* h1   = symaddr(g_h1);
    float* s2   = symaddr(g_s2);
    float* h2   = symaddr(g_h2);

    const int gridR = Bb * 56;
    const int gridG = Mm / 64;           // 1568

    auto setsm = [](const void* f) {
        cudaFuncSetAttribute(f, cudaFuncAttributeMaxDynamicSharedMemorySize, SM_ALL);
    };
    setsm((const void*)gemm_k<128, EPI_GELU, 0, false, false>);
    setsm((const void*)gemm_k<128, EPI_RES,  0, false, false>);
    setsm((const void*)gemm_k<128, EPI_BIAS, 0, true,  true >);
    setsm((const void*)gemm_k<256, EPI_RES,  2, false, false>);
    setsm((const void*)gemm_k<256, EPI_BIAS, 3, false, false>);
    cudaFuncSetAttribute(attn_k, cudaFuncAttributeMaxDynamicSharedMemorySize, ATTN_SMEM);

    #define GEMM_ARGS(A0,A1,B,bias,res,q0,q1,q2,q3,C) \
        A0, A1, B, nullptr, nullptr, bias, nullptr, nullptr, res, q0, q1, q2, q3, C, nullptr, nullptr

    // Branch 1
    roll_k<0><<<gridR, 256>>>(x, t0);
    gemm_k<128, EPI_GELU, 0, false, false><<<gridG, 256, SM_ALL>>>(
        GEMM_ARGS(t0, nullptr, fc1_w, fc1_b, nullptr, nullptr, nullptr, nullptr, nullptr, t1));
    roll_k<1><<<gridR, 256>>>(t1, t0);
    gemm_k<128, EPI_RES, 0, false, false><<<gridG, 256, SM_ALL>>>(
        GEMM_ARGS(t0, nullptr, fc2_w, fc2_b, x, nullptr, nullptr, nullptr, nullptr, x1a));

    // Branch 2
    roll_k<2><<<gridR, 256>>>(x, t0);
    gemm_k<128, EPI_GELU, 0, false, false><<<gridG, 256, SM_ALL>>>(
        GEMM_ARGS(t0, nullptr, fc3_w, fc3_b, nullptr, nullptr, nullptr, nullptr, nullptr, t1));
    roll_k<0><<<gridR, 256>>>(t1, t0);
    gemm_k<128, EPI_RES, 0, false, false><<<gridG, 256, SM_ALL>>>(
        GEMM_ARGS(t0, nullptr, fc4_w, fc4_b, x, nullptr, nullptr, nullptr, nullptr, x2a));

    // LN stats + fc5 (LN folded into A-gather) + residual -> t0
    ln_stats_k<<<Mm / 8, 256>>>(x1a, x2a, mean, rstd);
    gemm_k<256, EPI_RES, 2, false, false><<<gridG, 256, SM_ALL>>>(
        x1a, x2a, fc5_w, nullptr, nullptr, fc5_b, nullptr, nullptr, x,
        mean, rstd, ln_w, ln_b, t0, nullptr, nullptr);

    // q/k/v in one launch (grid.y selects weight/bias/output)
    gemm_k<128, EPI_BIAS, 0, true, true><<<dim3(gridG, 3), 256, SM_ALL>>>(
        x, nullptr, q_w, k_w, v_w, q_b, k_b, v_b, nullptr,
        nullptr, nullptr, nullptr, nullptr, qb, kb, vb);

    // Window attention (tensor cores)
    attn_k<<<2048, 256, ATTN_SMEM>>>(qb, kb, vb, att);

    // BN1 stats -> reduce -> BN2 stats (read-only, relu(bn1) on the fly) -> reduce
    bn_stats_k<<<784, 256>>>(att, part);
    bn_reduce_k<<<1, 128>>>(part, bn1_g, bn1_b, s1, h1);
    bn2_stats_k<<<784, 256>>>(att, s1, h1, part);
    bn_reduce_k<<<1, 128>>>(part, bn2_g, bn2_b, s2, h2);

    // Final: out = [x1 | relu(bn1(att))*bn2] @ fc6 + b  (full fold in A-gather)
    gemm_k<256, EPI_BIAS, 3, false, false><<<gridG, 256, SM_ALL>>>(
        t0, att, fc6_w, nullptr, nullptr, fc6_b, nullptr, nullptr, nullptr,
        s1, h1, s2, h2, (float*)d_out, nullptr, nullptr);
}

// round 11
// speedup vs baseline: 1.1355x; 1.1355x over previous
#include <cuda_runtime.h>
#include <math.h>
#include <stdint.h>

constexpr int Bb = 32;
constexpr int Hh = 56;
constexpr int Ww = 56;
constexpr int Cc = 128;
constexpr int Nn = Hh * Ww;              // 3136
constexpr int Mm = Bb * Nn;              // 100352
constexpr size_t MC = (size_t)Mm * Cc;

__device__ float g_t0[MC];
__device__ float g_t1[MC];
__device__ float g_x1a[MC];
__device__ float g_x2a[MC];
__device__ float g_q[MC];
__device__ float g_k[MC];
__device__ float g_v[MC];
__device__ float g_att[MC];
__device__ float g_stats[2 * Mm];        // LN mean | rstd
__device__ float g_part[784 * 256];
__device__ float g_s1[Cc];
__device__ float g_h1[Cc];
__device__ float g_s2[Cc];
__device__ float g_h2[Cc];

__device__ __forceinline__ float tf32r(float x) {
    uint32_t u;
    asm("cvt.rna.tf32.f32 %0, %1;" : "=r"(u) : "f"(x));
    return __uint_as_float(u);
}

__device__ __forceinline__ void mma_tf32(float* c, const float4& a, const float2& b) {
    asm volatile(
        "mma.sync.aligned.m16n8k8.row.col.f32.tf32.tf32.f32 "
        "{%0,%1,%2,%3}, {%4,%5,%6,%7}, {%8,%9}, {%0,%1,%2,%3};"
        : "+f"(c[0]), "+f"(c[1]), "+f"(c[2]), "+f"(c[3])
        : "r"(__float_as_uint(a.x)), "r"(__float_as_uint(a.y)),
          "r"(__float_as_uint(a.z)), "r"(__float_as_uint(a.w)),
          "r"(__float_as_uint(b.x)), "r"(__float_as_uint(b.y)));
}

// ---------------------------------------------------------------------------
// Per-channel roll. MODE 0: H,+c  1: W,+c  2: W,-c
// ---------------------------------------------------------------------------
template <int MODE>
__launch_bounds__(256)
__global__ void roll_k(const float* __restrict__ in, float* __restrict__ out) {
    __shared__ float tile[56 * 128];
    const int tid = threadIdx.x;
    const int b = blockIdx.x / 56;
    const int f = blockIdx.x % 56;
    const size_t base   = (MODE == 0) ? ((size_t)b * Nn + f) * 128
                                      : ((size_t)(b * 56 + f) * 56) * 128;
    const int    stride = (MODE == 0) ? 56 * 128 : 128;

    #pragma unroll
    for (int e = tid; e < 56 * 32; e += 256) {
        int rowi = e >> 5, c4 = e & 31;
        ((float4*)tile)[rowi * 32 + c4] =
            *(const float4*)(in + base + (size_t)rowi * stride + c4 * 4);
    }
    __syncthreads();

    #pragma unroll
    for (int e = tid; e < 56 * 128; e += 256) {
        int pos = e >> 7, c = e & 127;
        int cm = c % 56;
        int src = (MODE == 2) ? pos + cm : pos - cm;
        if (src < 0) src += 56;
        if (src >= 56) src -= 56;
        out[base + (size_t)pos * stride + c] = tile[src * 128 + c];
    }
}

// ---------------------------------------------------------------------------
// Fused dual roll of x: out0 = roll H,+c   out2 = roll W,-c  (reads x once)
// Tile = one batch image, 8 channels: [56 h][56 w][8 c] = 100 KB smem.
// Scatter reads are bank-conflict-free: bank = 8*(w mod 4)+ci (56 % 4 == 0).
// ---------------------------------------------------------------------------
constexpr int ROLL02_SMEM = 56 * 56 * 8 * 4;

__launch_bounds__(256)
__global__ void roll02_k(const float* __restrict__ in, float* __restrict__ out0,
                         float* __restrict__ out2) {
    extern __shared__ float tile[];     // [56*56][8]
    const int tid = threadIdx.x;
    const int b  = blockIdx.x >> 4;
    const int cg = blockIdx.x & 15;
    const int c0 = cg * 8;
    const size_t base = (size_t)b * Nn * 128;

    for (int e = tid; e < 56 * 56 * 2; e += 256) {
        int pos = e >> 1, half = e & 1;
        float4 v = *(const float4*)(in + base + (size_t)pos * 128 + c0 + half * 4);
        *(float4*)(tile + pos * 8 + half * 4) = v;
    }
    __syncthreads();

    for (int e = tid; e < 56 * 56 * 8; e += 256) {
        int pos = e >> 3, ci = e & 7;
        int h = pos / 56, w = pos - h * 56;
        int cm = (c0 + ci) % 56;
        int hs = h - cm; if (hs < 0) hs += 56;
        int ws = w + cm; if (ws >= 56) ws -= 56;
        out0[base + (size_t)pos * 128 + c0 + ci] = tile[(hs * 56 + w) * 8 + ci];
        out2[base + (size_t)pos * 128 + c0 + ci] = tile[(h * 56 + ws) * 8 + ci];
    }
}

// ---------------------------------------------------------------------------
// TF32 GEMM (R9 measured-best config). Coalesced LDG.128 -> XOR-swizzled smem
// A (conflict-free both sides). Register prefetch distance 2, ONE barrier per
// slice. B resident fragment-order smem (64 KB chunk; K=256 swaps once).
// AMODE: 0 plain A[M,K]; 1 split+per-col affine on A1; 2 split+LN fold;
//        3 split+relu(bn1)*bn2 fold. QKV: grid.y selects B/bias/C.
// ---------------------------------------------------------------------------
enum { EPI_GELU = 0, EPI_BIAS = 1, EPI_RES = 2 };
constexpr int SM_ALL = 16 * 16 * 32 * 8 + 2 * 128 * 32 * 4;   // 64KB B + 32KB A

template <int K, int EPI, int AMODE, bool BT, bool QKV>
__launch_bounds__(256, 2)
__global__ void gemm_k(const float* __restrict__ A0, const float* __restrict__ A1,
                       const float* __restrict__ B0, const float* __restrict__ B1,
                       const float* __restrict__ B2,
                       const float* __restrict__ bias0, const float* __restrict__ bias1,
                       const float* __restrict__ bias2,
                       const float* __restrict__ res,
                       const float* __restrict__ p0, const float* __restrict__ p1,
                       const float* __restrict__ p2, const float* __restrict__ p3,
                       float* __restrict__ C0, float* __restrict__ C1,
                       float* __restrict__ C2) {
    extern __shared__ float smem[];
    float2* Bs = (float2*)smem;                 // [16 k8][16 nt][32 lane]
    float*  As = smem + 16384;                  // 2 bufs x 128 rows x 32 (swizzled)

    const float* Bm = B0;
    const float* bias = bias0;
    float* Cm = C0;
    if (QKV) {
        int y = blockIdx.y;
        if (y == 1) { Bm = B1; bias = bias1; Cm = C1; }
        else if (y == 2) { Bm = B2; bias = bias2; Cm = C2; }
    }

    const int tid  = threadIdx.x;
    const int lane = tid & 31;
    const int wid  = tid >> 5;
    const int wm   = wid & 3;
    const int wn   = wid >> 2;
    const int row0 = blockIdx.x * 128;
    const int lr   = lane >> 2;
    const int lc   = lane & 3;

    auto loadB = [&](int ko) {
        for (int frag = wid; frag < 256; frag += 8) {
            int k8l = frag >> 4, nt = frag & 15;
            int kk = ko + k8l * 8 + lc, n = nt * 8 + lr;
            float b0v, b1v;
            if (BT) { b0v = Bm[(size_t)n * K + kk];   b1v = Bm[(size_t)n * K + kk + 4]; }
            else    { b0v = Bm[(size_t)kk * 128 + n]; b1v = Bm[(size_t)(kk + 4) * 128 + n]; }
            Bs[frag * 32 + lane] = make_float2(tf32r(b0v), tf32r(b1v));
        }
    };

    // ---- A producer: thread loads rows (tid>>3)+{0,32,64,96}, c4 block tid&7
    const int arow = tid >> 3;
    const int ac4  = tid & 7;
    float mrow[4], rrow[4];
    if (AMODE == 2) {
        #pragma unroll
        for (int i = 0; i < 4; i++) {
            int gr = row0 + arow + i * 32;
            mrow[i] = p0[gr];
            rrow[i] = p1[gr];
        }
    }

    auto fetch4 = [&](int i, int c) -> float4 {
        int gr = row0 + arow + i * 32;
        float4 v;
        if (AMODE == 0) {
            v = *(const float4*)(A0 + (size_t)gr * K + c);
        } else {
            v = (c < 128) ? *(const float4*)(A0 + (size_t)gr * 128 + c)
                          : *(const float4*)(A1 + (size_t)gr * 128 + (c - 128));
            if (AMODE == 1) {
                if (c >= 128) {
                    float4 s = *(const float4*)(p0 + c - 128);
                    float4 h = *(const float4*)(p1 + c - 128);
                    v.x = v.x * s.x + h.x; v.y = v.y * s.y + h.y;
                    v.z = v.z * s.z + h.z; v.w = v.w * s.w + h.w;
                }
            } else if (AMODE == 2) {
                float4 g = *(const float4*)(p2 + c);
                float4 bb = *(const float4*)(p3 + c);
                float mn = mrow[i], rs = rrow[i];
                v.x = (v.x - mn) * rs * g.x + bb.x;
                v.y = (v.y - mn) * rs * g.y + bb.y;
                v.z = (v.z - mn) * rs * g.z + bb.z;
                v.w = (v.w - mn) * rs * g.w + bb.w;
            } else {            // AMODE 3: relu(bn1)*bn2 fold on A1
                if (c >= 128) {
                    float4 sa = *(const float4*)(p0 + c - 128);
                    float4 ha = *(const float4*)(p1 + c - 128);
                    float4 sb = *(const float4*)(p2 + c - 128);
                    float4 hb = *(const float4*)(p3 + c - 128);
                    v.x = fmaxf(v.x * sa.x + ha.x, 0.f) * sb.x + hb.x;
                    v.y = fmaxf(v.y * sa.y + ha.y, 0.f) * sb.y + hb.y;
                    v.z = fmaxf(v.z * sa.z + ha.z, 0.f) * sb.z + hb.z;
                    v.w = fmaxf(v.w * sa.w + ha.w, 0.f) * sb.w + hb.w;
                }
            }
        }
        return make_float4(tf32r(v.x), tf32r(v.y), tf32r(v.z), tf32r(v.w));
    };

    float4 pa[2][4];
    auto gather = [&](int kc, int set) {
        int c = kc + ac4 * 4;
        #pragma unroll
        for (int i = 0; i < 4; i++) pa[set][i] = fetch4(i, c);
    };

    loadB(0);
    gather(0, 0);
    gather(32, 1);

    float acc[2][8][4] = {};
    constexpr int NS = K / 32;

    #pragma unroll
    for (int s = 0; s < NS; s++) {
        const int set = s & 1;
        const int bo = set * 4096;
        // STS swizzled: addr(row,c4) = row*32 + 4*(c4 ^ (row&7))
        #pragma unroll
        for (int i = 0; i < 4; i++) {
            int row = arow + i * 32;
            *(float4*)(As + bo + row * 32 + 4 * (ac4 ^ (row & 7))) = pa[set][i];
        }
        __syncthreads();
        if (K > 128 && s == 4) {            // swap B chunk (all warps past mma(3))
            loadB(128);
            __syncthreads();
        }
        if (s + 2 < NS) gather((s + 2) * 32, set);
        const int kb = (s & 3) * 4;
        #pragma unroll
        for (int k8 = 0; k8 < 4; k8++) {
            float4 av[2];
            #pragma unroll
            for (int mt2 = 0; mt2 < 2; mt2++) {
                int r = wm * 32 + mt2 * 16 + lr;
                int s0 = 4 * ((2 * k8) ^ lr) + lc;
                int s1 = 4 * ((2 * k8 + 1) ^ lr) + lc;
                const float* b1p = As + bo + r * 32;
                const float* b2p = As + bo + (r + 8) * 32;
                av[mt2] = make_float4(b1p[s0], b2p[s0], b1p[s1], b2p[s1]);
            }
            #pragma unroll
            for (int u = 0; u < 8; u++) {
                float2 b = Bs[((kb + k8) * 16 + wn * 8 + u) * 32 + lane];
                mma_tf32(acc[0][u], av[0], b);
                mma_tf32(acc[1][u], av[1], b);
            }
        }
    }

    const int ec = lc * 2;
    #pragma unroll
    for (int t = 0; t < 2; t++) {
        int m0 = row0 + wm * 32 + t * 16 + lr;
        #pragma unroll
        for (int u = 0; u < 8; u++) {
            int n = wn * 64 + u * 8 + ec;
            float b0 = bias[n], b1 = bias[n + 1];
            float v0 = acc[t][u][0] + b0;
            float v1 = acc[t][u][1] + b1;
            float v2 = acc[t][u][2] + b0;
            float v3 = acc[t][u][3] + b1;
            if (EPI == EPI_GELU) {
                v0 = 0.5f * v0 * (1.0f + erff(v0 * 0.70710678f));
                v1 = 0.5f * v1 * (1.0f + erff(v1 * 0.70710678f));
                v2 = 0.5f * v2 * (1.0f + erff(v2 * 0.70710678f));
                v3 = 0.5f * v3 * (1.0f + erff(v3 * 0.70710678f));
            } else if (EPI == EPI_RES) {
                float2 r0 = *(const float2*)(res + (size_t)m0 * 128 + n);
                float2 rr = *(const float2*)(res + (size_t)(m0 + 8) * 128 + n);
                v0 += r0.x; v1 += r0.y; v2 += rr.x; v3 += rr.y;
            }
            *(float2*)(Cm + (size_t)m0 * 128 + n)       = make_float2(v0, v1);
            *(float2*)(Cm + (size_t)(m0 + 8) * 128 + n) = make_float2(v2, v3);
        }
    }
}

// ---------------------------------------------------------------------------
// LayerNorm stats only: per-token mean & rstd over the 256-wide concat
// ---------------------------------------------------------------------------
__global__ void ln_stats_k(const float* __restrict__ x1a, const float* __restrict__ x2a,
                           float* __restrict__ mean, float* __restrict__ rstd) {
    int warp = (blockIdx.x * blockDim.x + threadIdx.x) >> 5;
    int lane = threadIdx.x & 31;
    if (warp >= Mm) return;
    float s = 0.f, sq = 0.f;
    #pragma unroll
    for (int kq = 0; kq < 4; kq++) {
        float a = x1a[(size_t)warp * 128 + lane + 32 * kq];
        float b = x2a[(size_t)warp * 128 + lane + 32 * kq];
        s += a + b; sq += a * a + b * b;
    }
    #pragma unroll
    for (int o = 16; o > 0; o >>= 1) {
        s  += __shfl_xor_sync(0xffffffffu, s, o);
        sq += __shfl_xor_sync(0xffffffffu, sq, o);
    }
    if (lane == 0) {
        float mu = s * (1.f / 256.f);
        float var = sq * (1.f / 256.f) - mu * mu;
        mean[warp] = mu;
        rstd[warp] = rsqrtf(var + 1e-5f);
    }
}

// ---------------------------------------------------------------------------
// Window attention on tensor cores (validated in R5)
// ---------------------------------------------------------------------------
constexpr int QS_STRIDE = 132;
constexpr int VS_STRIDE = 136;
constexpr int PS_STRIDE = 68;
constexpr int ATTN_SMEM = (2 * 64 * QS_STRIDE + 64 * VS_STRIDE + 64 * PS_STRIDE) * 4;

__launch_bounds__(256)
__global__ void attn_k(const float* __restrict__ q, const float* __restrict__ k,
                       const float* __restrict__ v, float* __restrict__ out) {
    extern __shared__ float sm[];
    float* Qs = sm;
    float* Ks = Qs + 64 * QS_STRIDE;
    float* Vs = Ks + 64 * QS_STRIDE;
    float* Ps = Vs + 64 * VS_STRIDE;

    const int widx = blockIdx.x;
    const int b = widx >> 6, wh = (widx >> 3) & 7, ww = widx & 7;
    const int tid  = threadIdx.x;
    const int lane = tid & 31, w = tid >> 5;
    const int wm = w & 3, wn = w >> 2;
    const int lr = lane >> 2, lc = lane & 3;

    auto grow = [&](int i) -> size_t {
        return ((size_t)(b * Nn + (wh * 7 + i / 7) * 56 + ww * 7 + (i % 7))) * 128;
    };

    for (int e = tid; e < 49 * 32; e += 256) {
        int i = e >> 5, c4 = (e & 31) * 4;
        size_t g = grow(i) + c4;
        float4 a  = *(const float4*)(q + g);
        float4 kk = *(const float4*)(k + g);
        float4 vv = *(const float4*)(v + g);
        *(float4*)(Qs + i * QS_STRIDE + c4) =
            make_float4(tf32r(a.x), tf32r(a.y), tf32r(a.z), tf32r(a.w));
        *(float4*)(Ks + i * QS_STRIDE + c4) =
            make_float4(tf32r(kk.x), tf32r(kk.y), tf32r(kk.z), tf32r(kk.w));
        *(float4*)(Vs + i * VS_STRIDE + c4) =
            make_float4(tf32r(vv.x), tf32r(vv.y), tf32r(vv.z), tf32r(vv.w));
    }
    for (int e = tid; e < 15 * QS_STRIDE; e += 256) {
        Qs[49 * QS_STRIDE + e] = 0.f;
        Ks[49 * QS_STRIDE + e] = 0.f;
    }
    for (int e = tid; e < 15 * VS_STRIDE; e += 256) Vs[49 * VS_STRIDE + e] = 0.f;
    __syncthreads();

    float acc[4][4] = {};
    #pragma unroll
    for (int k8 = 0; k8 < 16; k8++) {
        int r = wm * 16 + lr, c = k8 * 8 + lc;
        float4 a = make_float4(Qs[r * QS_STRIDE + c],     Qs[(r + 8) * QS_STRIDE + c],
                               Qs[r * QS_STRIDE + c + 4], Qs[(r + 8) * QS_STRIDE + c + 4]);
        #pragma unroll
        for (int u = 0; u < 4; u++) {
            int n = wn * 32 + u * 8 + lr;
            float2 bf = make_float2(Ks[n * QS_STRIDE + c], Ks[n * QS_STRIDE + c + 4]);
            mma_tf32(acc[u], a, bf);
        }
    }
    #pragma unroll
    for (int u = 0; u < 4; u++) {
        int r = wm * 16 + lr, n = wn * 32 + u * 8 + lc * 2;
        *(float2*)(Ps + r * PS_STRIDE + n)       = make_float2(acc[u][0], acc[u][1]);
        *(float2*)(Ps + (r + 8) * PS_STRIDE + n) = make_float2(acc[u][2], acc[u][3]);
    }
    __syncthreads();

    if (tid < 49) {
        const float scale = 0.08838834764831845f;
        float* r = Ps + tid * PS_STRIDE;
        float mx = r[0];
        #pragma unroll 7
        for (int j = 1; j < 49; j++) mx = fmaxf(mx, r[j]);
        float s = 0.f;
        #pragma unroll 7
        for (int j = 0; j < 49; j++) { float e = expf((r[j] - mx) * scale); r[j] = e; s += e; }
        float inv = 1.f / s;
        #pragma unroll 7
        for (int j = 0; j < 49; j++) r[j] = tf32r(r[j] * inv);
        #pragma unroll
        for (int j = 49; j < 64; j++) r[j] = 0.f;
    }
    __syncthreads();

    float o[8][4] = {};
    #pragma unroll
    for (int k8 = 0; k8 < 8; k8++) {
        int r = wm * 16 + lr, c = k8 * 8 + lc;
        float4 a = make_float4(Ps[r * PS_STRIDE + c],     Ps[(r + 8) * PS_STRIDE + c],
                               Ps[r * PS_STRIDE + c + 4], Ps[(r + 8) * PS_STRIDE + c + 4]);
        #pragma unroll
        for (int u = 0; u < 8; u++) {
            int n = wn * 64 + u * 8 + lr;
            float2 bf = make_float2(Vs[c * VS_STRIDE + n], Vs[(c + 4) * VS_STRIDE + n]);
            mma_tf32(o[u], a, bf);
        }
    }
    int r0 = wm * 16 + lr;
    #pragma unroll
    for (int u = 0; u < 8; u++) {
        int n = wn * 64 + u * 8 + lc * 2;
        if (r0 < 49)     *(float2*)(out + grow(r0) + n)     = make_float2(o[u][0], o[u][1]);
        if (r0 + 8 < 49) *(float2*)(out + grow(r0 + 8) + n) = make_float2(o[u][2], o[u][3]);
    }
}

// ---------------------------------------------------------------------------
// BatchNorm pieces
// ---------------------------------------------------------------------------
__global__ void bn_stats_k(const float* __restrict__ x, float* __restrict__ part) {
    int c = threadIdx.x & 127;
    int half = threadIdx.x >> 7;
    float s = 0.f, sq = 0.f;
    int rbeg = blockIdx.x * 128 + half;
    int rend = blockIdx.x * 128 + 128;
    for (int r = rbeg; r < rend; r += 2) {
        float vv = x[(size_t)r * 128 + c];
        s += vv; sq += vv * vv;
    }
    __shared__ float sh[512];
    sh[threadIdx.x] = s;
    sh[256 + threadIdx.x] = sq;
    __syncthreads();
    if (half == 0) {
        part[blockIdx.x * 256 + c]       = sh[c] + sh[128 + c];
        part[blockIdx.x * 256 + 128 + c] = sh[256 + c] + sh[256 + 128 + c];
    }
}

// read-only: stats of relu(bn1(x))
__global__ void bn2_stats_k(const float* __restrict__ x,
                            const float* __restrict__ s1, const float* __restrict__ h1,
                            float* __restrict__ part) {
    int c = threadIdx.x & 127;
    int half = threadIdx.x >> 7;
    float sc = s1[c], sh_ = h1[c];
    float s = 0.f, sq = 0.f;
    int rbeg = blockIdx.x * 128 + half;
    int rend = blockIdx.x * 128 + 128;
    for (int r = rbeg; r < rend; r += 2) {
        float vv = fmaxf(x[(size_t)r * 128 + c] * sc + sh_, 0.f);
        s += vv; sq += vv * vv;
    }
    __shared__ float shm[512];
    shm[threadIdx.x] = s;
    shm[256 + threadIdx.x] = sq;
    __syncthreads();
    if (half == 0) {
        part[blockIdx.x * 256 + c]       = shm[c] + shm[128 + c];
        part[blockIdx.x * 256 + 128 + c] = shm[256 + c] + shm[256 + 128 + c];
    }
}

__global__ void bn_reduce_k(const float* __restrict__ part, const float* __restrict__ g,
                            const float* __restrict__ beta, float* __restrict__ scale,
                            float* __restrict__ shift) {
    int c = threadIdx.x;
    float s = 0.f, sq = 0.f;
    for (int i = 0; i < 784; i++) {
        s  += part[i * 256 + c];
        sq += part[i * 256 + 128 + c];
    }
    float mean = s / (float)Mm;
    float var  = sq / (float)Mm - mean * mean;
    float sc_  = g[c] * rsqrtf(var + 1e-5f);
    scale[c] = sc_;
    shift[c] = beta[c] - mean * sc_;
}

// ---------------------------------------------------------------------------
// Host launch
// ---------------------------------------------------------------------------
static float* symaddr(const void* devsym) {
    void* p = nullptr;
    cudaGetSymbolAddress(&p, devsym);
    return (float*)p;
}

extern "C" void kernel_launch(void* const* d_in, const int* in_sizes, int n_in,
                              void* d_out, int out_size) {
    const float* x     = (const float*)d_in[0];
    const float* fc1_w = (const float*)d_in[1];
    const float* fc1_b = (const float*)d_in[2];
    const float* fc2_w = (const float*)d_in[3];
    const float* fc2_b = (const float*)d_in[4];
    const float* fc3_w = (const float*)d_in[5];
    const float* fc3_b = (const float*)d_in[6];
    const float* fc4_w = (const float*)d_in[7];
    const float* fc4_b = (const float*)d_in[8];
    const float* fc5_w = (const float*)d_in[9];
    const float* fc5_b = (const float*)d_in[10];
    const float* fc6_w = (const float*)d_in[11];
    const float* fc6_b = (const float*)d_in[12];
    const float* ln_w  = (const float*)d_in[13];
    const float* ln_b  = (const float*)d_in[14];
    const float* q_w   = (const float*)d_in[15];
    const float* q_b   = (const float*)d_in[16];
    const float* k_w   = (const float*)d_in[17];
    const float* k_b   = (const float*)d_in[18];
    const float* v_w   = (const float*)d_in[19];
    const float* v_b   = (const float*)d_in[20];
    const float* bn1_g = (const float*)d_in[21];
    const float* bn1_b = (const float*)d_in[22];
    const float* bn2_g = (const float*)d_in[23];
    const float* bn2_b = (const float*)d_in[24];

    float* t0   = symaddr(g_t0);
    float* t1   = symaddr(g_t1);
    float* x1a  = symaddr(g_x1a);
    float* x2a  = symaddr(g_x2a);
    float* qb   = symaddr(g_q);
    float* kb   = symaddr(g_k);
    float* vb   = symaddr(g_v);
    float* att  = symaddr(g_att);
    float* stat = symaddr(g_stats);
    float* mean = stat;
    float* rstd = stat + Mm;
    float* part = symaddr(g_part);
    float* s1   = symaddr(g_s1);
    float* h1   = symaddr(g_h1);
    float* s2   = symaddr(g_s2);
    float* h2   = symaddr(g_h2);

    const int gridR = Bb * 56;
    const int gridG = Mm / 128;          // 784

    auto setsm = [](const void* f) {
        cudaFuncSetAttribute(f, cudaFuncAttributeMaxDynamicSharedMemorySize, SM_ALL);
    };
    setsm((const void*)gemm_k<128, EPI_GELU, 0, false, false>);
    setsm((const void*)gemm_k<128, EPI_RES,  0, false, false>);
    setsm((const void*)gemm_k<128, EPI_BIAS, 0, true,  true >);
    setsm((const void*)gemm_k<256, EPI_RES,  2, false, false>);
    setsm((const void*)gemm_k<256, EPI_BIAS, 3, false, false>);
    cudaFuncSetAttribute(attn_k, cudaFuncAttributeMaxDynamicSharedMemorySize, ATTN_SMEM);
    cudaFuncSetAttribute(roll02_k, cudaFuncAttributeMaxDynamicSharedMemorySize, ROLL02_SMEM);

    #define GEMM_ARGS(A0,A1,B,bias,res,q0,q1,q2,q3,C) \
        A0, A1, B, nullptr, nullptr, bias, nullptr, nullptr, res, q0, q1, q2, q3, C, nullptr, nullptr

    // Fused dual roll: x -> t0 (H,+c) and x2a (W,-c)
    roll02_k<<<Bb * 16, 256, ROLL02_SMEM>>>(x, t0, x2a);

    // Branch 1
    gemm_k<128, EPI_GELU, 0, false, false><<<gridG, 256, SM_ALL>>>(
        GEMM_ARGS(t0, nullptr, fc1_w, fc1_b, nullptr, nullptr, nullptr, nullptr, nullptr, t1));
    roll_k<1><<<gridR, 256>>>(t1, t0);
    gemm_k<128, EPI_RES, 0, false, false><<<gridG, 256, SM_ALL>>>(
        GEMM_ARGS(t0, nullptr, fc2_w, fc2_b, x, nullptr, nullptr, nullptr, nullptr, x1a));

    // Branch 2 (input x2a from fused roll)
    gemm_k<128, EPI_GELU, 0, false, false><<<gridG, 256, SM_ALL>>>(
        GEMM_ARGS(x2a, nullptr, fc3_w, fc3_b, nullptr, nullptr, nullptr, nullptr, nullptr, t1));
    roll_k<0><<<gridR, 256>>>(t1, t0);
    gemm_k<128, EPI_RES, 0, false, false><<<gridG, 256, SM_ALL>>>(
        GEMM_ARGS(t0, nullptr, fc4_w, fc4_b, x, nullptr, nullptr, nullptr, nullptr, x2a));

    // LN stats + fc5 (LN folded into A-gather) + residual -> t0
    ln_stats_k<<<Mm / 8, 256>>>(x1a, x2a, mean, rstd);
    gemm_k<256, EPI_RES, 2, false, false><<<gridG, 256, SM_ALL>>>(
        x1a, x2a, fc5_w, nullptr, nullptr, fc5_b, nullptr, nullptr, x,
        mean, rstd, ln_w, ln_b, t0, nullptr, nullptr);

    // q/k/v in one launch (grid.y selects weight/bias/output)
    gemm_k<128, EPI_BIAS, 0, true, true><<<dim3(gridG, 3), 256, SM_ALL>>>(
        x, nullptr, q_w, k_w, v_w, q_b, k_b, v_b, nullptr,
        nullptr, nullptr, nullptr, nullptr, qb, kb, vb);

    // Window attention (tensor cores)
    attn_k<<<2048, 256, ATTN_SMEM>>>(qb, kb, vb, att);

    // BN1 stats -> reduce -> BN2 stats (read-only, relu(bn1) on the fly) -> reduce
    bn_stats_k<<<784, 256>>>(att, part);
    bn_reduce_k<<<1, 128>>>(part, bn1_g, bn1_b, s1, h1);
    bn2_stats_k<<<784, 256>>>(att, s1, h1, part);
    bn_reduce_k<<<1, 128>>>(part, bn2_g, bn2_b, s2, h2);

    // Final: out = [x1 | relu(bn1(att))*bn2] @ fc6 + b  (full fold in A-gather)
    gemm_k<256, EPI_BIAS, 3, false, false><<<gridG, 256, SM_ALL>>>(
        t0, att, fc6_w, nullptr, nullptr, fc6_b, nullptr, nullptr, nullptr,
        s1, h1, s2, h2, (float*)d_out, nullptr, nullptr);
}

// round 12
// speedup vs baseline: 1.1692x; 1.0296x over previous
#include <cuda_runtime.h>
#include <math.h>
#include <stdint.h>

constexpr int Bb = 32;
constexpr int Hh = 56;
constexpr int Ww = 56;
constexpr int Cc = 128;
constexpr int Nn = Hh * Ww;              // 3136
constexpr int Mm = Bb * Nn;              // 100352
constexpr size_t MC = (size_t)Mm * Cc;

__device__ float g_t0[MC];
__device__ float g_t1[MC];
__device__ float g_x1a[MC];
__device__ float g_x2a[MC];
__device__ float g_q[MC];
__device__ float g_k[MC];
__device__ float g_v[MC];
__device__ float g_att[MC];
__device__ float g_stats[2 * Mm];        // LN mean | rstd
__device__ float g_part[784 * 256];
__device__ float g_s1[Cc];
__device__ float g_h1[Cc];
__device__ float g_s2[Cc];
__device__ float g_h2[Cc];

__device__ __forceinline__ float tf32r(float x) {
    uint32_t u;
    asm("cvt.rna.tf32.f32 %0, %1;" : "=r"(u) : "f"(x));
    return __uint_as_float(u);
}

__device__ __forceinline__ void mma_tf32(float* c, const float4& a, const float2& b) {
    asm volatile(
        "mma.sync.aligned.m16n8k8.row.col.f32.tf32.tf32.f32 "
        "{%0,%1,%2,%3}, {%4,%5,%6,%7}, {%8,%9}, {%0,%1,%2,%3};"
        : "+f"(c[0]), "+f"(c[1]), "+f"(c[2]), "+f"(c[3])
        : "r"(__float_as_uint(a.x)), "r"(__float_as_uint(a.y)),
          "r"(__float_as_uint(a.z)), "r"(__float_as_uint(a.w)),
          "r"(__float_as_uint(b.x)), "r"(__float_as_uint(b.y)));
}

// ---------------------------------------------------------------------------
// Per-channel roll. MODE 0: H,+c  1: W,+c  2: W,-c
// ---------------------------------------------------------------------------
template <int MODE>
__launch_bounds__(256)
__global__ void roll_k(const float* __restrict__ in, float* __restrict__ out) {
    __shared__ float tile[56 * 128];
    const int tid = threadIdx.x;
    const int b = blockIdx.x / 56;
    const int f = blockIdx.x % 56;
    const size_t base   = (MODE == 0) ? ((size_t)b * Nn + f) * 128
                                      : ((size_t)(b * 56 + f) * 56) * 128;
    const int    stride = (MODE == 0) ? 56 * 128 : 128;

    #pragma unroll
    for (int e = tid; e < 56 * 32; e += 256) {
        int rowi = e >> 5, c4 = e & 31;
        ((float4*)tile)[rowi * 32 + c4] =
            *(const float4*)(in + base + (size_t)rowi * stride + c4 * 4);
    }
    __syncthreads();

    #pragma unroll
    for (int e = tid; e < 56 * 128; e += 256) {
        int pos = e >> 7, c = e & 127;
        int cm = c % 56;
        int src = (MODE == 2) ? pos + cm : pos - cm;
        if (src < 0) src += 56;
        if (src >= 56) src -= 56;
        out[base + (size_t)pos * stride + c] = tile[src * 128 + c];
    }
}

// ---------------------------------------------------------------------------
// TF32 GEMM (R9 measured-best config). Coalesced LDG.128 -> XOR-swizzled smem
// A (conflict-free both sides). Register prefetch distance 2, ONE barrier per
// slice. B resident fragment-order smem (64 KB chunk; K=256 swaps once).
// AMODE: 0 plain A[M,K]; 1 split+per-col affine on A1; 2 split+LN fold;
//        3 split+relu(bn1)*bn2 fold. QKV: grid.y selects B/bias/C.
// ---------------------------------------------------------------------------
enum { EPI_GELU = 0, EPI_BIAS = 1, EPI_RES = 2 };
constexpr int SM_ALL = 16 * 16 * 32 * 8 + 2 * 128 * 32 * 4;   // 64KB B + 32KB A

template <int K, int EPI, int AMODE, bool BT, bool QKV>
__launch_bounds__(256, 2)
__global__ void gemm_k(const float* __restrict__ A0, const float* __restrict__ A1,
                       const float* __restrict__ B0, const float* __restrict__ B1,
                       const float* __restrict__ B2,
                       const float* __restrict__ bias0, const float* __restrict__ bias1,
                       const float* __restrict__ bias2,
                       const float* __restrict__ res,
                       const float* __restrict__ p0, const float* __restrict__ p1,
                       const float* __restrict__ p2, const float* __restrict__ p3,
                       float* __restrict__ C0, float* __restrict__ C1,
                       float* __restrict__ C2) {
    extern __shared__ float smem[];
    float2* Bs = (float2*)smem;                 // [16 k8][16 nt][32 lane]
    float*  As = smem + 16384;                  // 2 bufs x 128 rows x 32 (swizzled)

    const float* Bm = B0;
    const float* bias = bias0;
    float* Cm = C0;
    if (QKV) {
        int y = blockIdx.y;
        if (y == 1) { Bm = B1; bias = bias1; Cm = C1; }
        else if (y == 2) { Bm = B2; bias = bias2; Cm = C2; }
    }

    const int tid  = threadIdx.x;
    const int lane = tid & 31;
    const int wid  = tid >> 5;
    const int wm   = wid & 3;
    const int wn   = wid >> 2;
    const int row0 = blockIdx.x * 128;
    const int lr   = lane >> 2;
    const int lc   = lane & 3;

    auto loadB = [&](int ko) {
        for (int frag = wid; frag < 256; frag += 8) {
            int k8l = frag >> 4, nt = frag & 15;
            int kk = ko + k8l * 8 + lc, n = nt * 8 + lr;
            float b0v, b1v;
            if (BT) { b0v = Bm[(size_t)n * K + kk];   b1v = Bm[(size_t)n * K + kk + 4]; }
            else    { b0v = Bm[(size_t)kk * 128 + n]; b1v = Bm[(size_t)(kk + 4) * 128 + n]; }
            Bs[frag * 32 + lane] = make_float2(tf32r(b0v), tf32r(b1v));
        }
    };

    // ---- A producer: thread loads rows (tid>>3)+{0,32,64,96}, c4 block tid&7
    const int arow = tid >> 3;
    const int ac4  = tid & 7;
    float mrow[4], rrow[4];
    if (AMODE == 2) {
        #pragma unroll
        for (int i = 0; i < 4; i++) {
            int gr = row0 + arow + i * 32;
            mrow[i] = p0[gr];
            rrow[i] = p1[gr];
        }
    }

    auto fetch4 = [&](int i, int c) -> float4 {
        int gr = row0 + arow + i * 32;
        float4 v;
        if (AMODE == 0) {
            v = *(const float4*)(A0 + (size_t)gr * K + c);
        } else {
            v = (c < 128) ? *(const float4*)(A0 + (size_t)gr * 128 + c)
                          : *(const float4*)(A1 + (size_t)gr * 128 + (c - 128));
            if (AMODE == 1) {
                if (c >= 128) {
                    float4 s = *(const float4*)(p0 + c - 128);
                    float4 h = *(const float4*)(p1 + c - 128);
                    v.x = v.x * s.x + h.x; v.y = v.y * s.y + h.y;
                    v.z = v.z * s.z + h.z; v.w = v.w * s.w + h.w;
                }
            } else if (AMODE == 2) {
                float4 g = *(const float4*)(p2 + c);
                float4 bb = *(const float4*)(p3 + c);
                float mn = mrow[i], rs = rrow[i];
                v.x = (v.x - mn) * rs * g.x + bb.x;
                v.y = (v.y - mn) * rs * g.y + bb.y;
                v.z = (v.z - mn) * rs * g.z + bb.z;
                v.w = (v.w - mn) * rs * g.w + bb.w;
            } else {            // AMODE 3: relu(bn1)*bn2 fold on A1
                if (c >= 128) {
                    float4 sa = *(const float4*)(p0 + c - 128);
                    float4 ha = *(const float4*)(p1 + c - 128);
                    float4 sb = *(const float4*)(p2 + c - 128);
                    float4 hb = *(const float4*)(p3 + c - 128);
                    v.x = fmaxf(v.x * sa.x + ha.x, 0.f) * sb.x + hb.x;
                    v.y = fmaxf(v.y * sa.y + ha.y, 0.f) * sb.y + hb.y;
                    v.z = fmaxf(v.z * sa.z + ha.z, 0.f) * sb.z + hb.z;
                    v.w = fmaxf(v.w * sa.w + ha.w, 0.f) * sb.w + hb.w;
                }
            }
        }
        return make_float4(tf32r(v.x), tf32r(v.y), tf32r(v.z), tf32r(v.w));
    };

    float4 pa[2][4];
    auto gather = [&](int kc, int set) {
        int c = kc + ac4 * 4;
        #pragma unroll
        for (int i = 0; i < 4; i++) pa[set][i] = fetch4(i, c);
    };

    loadB(0);
    gather(0, 0);
    gather(32, 1);

    float acc[2][8][4] = {};
    constexpr int NS = K / 32;

    #pragma unroll
    for (int s = 0; s < NS; s++) {
        const int set = s & 1;
        const int bo = set * 4096;
        // STS swizzled: addr(row,c4) = row*32 + 4*(c4 ^ (row&7))
        #pragma unroll
        for (int i = 0; i < 4; i++) {
            int row = arow + i * 32;
            *(float4*)(As + bo + row * 32 + 4 * (ac4 ^ (row & 7))) = pa[set][i];
        }
        __syncthreads();
        if (K > 128 && s == 4) {            // swap B chunk (all warps past mma(3))
            loadB(128);
            __syncthreads();
        }
        if (s + 2 < NS) gather((s + 2) * 32, set);
        const int kb = (s & 3) * 4;
        #pragma unroll
        for (int k8 = 0; k8 < 4; k8++) {
            float4 av[2];
            #pragma unroll
            for (int mt2 = 0; mt2 < 2; mt2++) {
                int r = wm * 32 + mt2 * 16 + lr;
                int s0 = 4 * ((2 * k8) ^ lr) + lc;
                int s1 = 4 * ((2 * k8 + 1) ^ lr) + lc;
                const float* b1p = As + bo + r * 32;
                const float* b2p = As + bo + (r + 8) * 32;
                av[mt2] = make_float4(b1p[s0], b2p[s0], b1p[s1], b2p[s1]);
            }
            #pragma unroll
            for (int u = 0; u < 8; u++) {
                float2 b = Bs[((kb + k8) * 16 + wn * 8 + u) * 32 + lane];
                mma_tf32(acc[0][u], av[0], b);
                mma_tf32(acc[1][u], av[1], b);
            }
        }
    }

    const int ec = lc * 2;
    #pragma unroll
    for (int t = 0; t < 2; t++) {
        int m0 = row0 + wm * 32 + t * 16 + lr;
        #pragma unroll
        for (int u = 0; u < 8; u++) {
            int n = wn * 64 + u * 8 + ec;
            float b0 = bias[n], b1 = bias[n + 1];
            float v0 = acc[t][u][0] + b0;
            float v1 = acc[t][u][1] + b1;
            float v2 = acc[t][u][2] + b0;
            float v3 = acc[t][u][3] + b1;
            if (EPI == EPI_GELU) {
                v0 = 0.5f * v0 * (1.0f + erff(v0 * 0.70710678f));
                v1 = 0.5f * v1 * (1.0f + erff(v1 * 0.70710678f));
                v2 = 0.5f * v2 * (1.0f + erff(v2 * 0.70710678f));
                v3 = 0.5f * v3 * (1.0f + erff(v3 * 0.70710678f));
            } else if (EPI == EPI_RES) {
                float2 r0 = *(const float2*)(res + (size_t)m0 * 128 + n);
                float2 rr = *(const float2*)(res + (size_t)(m0 + 8) * 128 + n);
                v0 += r0.x; v1 += r0.y; v2 += rr.x; v3 += rr.y;
            }
            *(float2*)(Cm + (size_t)m0 * 128 + n)       = make_float2(v0, v1);
            *(float2*)(Cm + (size_t)(m0 + 8) * 128 + n) = make_float2(v2, v3);
        }
    }
}

// ---------------------------------------------------------------------------
// LayerNorm stats only: per-token mean & rstd over the 256-wide concat
// ---------------------------------------------------------------------------
__global__ void ln_stats_k(const float* __restrict__ x1a, const float* __restrict__ x2a,
                           float* __restrict__ mean, float* __restrict__ rstd) {
    int warp = (blockIdx.x * blockDim.x + threadIdx.x) >> 5;
    int lane = threadIdx.x & 31;
    if (warp >= Mm) return;
    float s = 0.f, sq = 0.f;
    #pragma unroll
    for (int kq = 0; kq < 4; kq++) {
        float a = x1a[(size_t)warp * 128 + lane + 32 * kq];
        float b = x2a[(size_t)warp * 128 + lane + 32 * kq];
        s += a + b; sq += a * a + b * b;
    }
    #pragma unroll
    for (int o = 16; o > 0; o >>= 1) {
        s  += __shfl_xor_sync(0xffffffffu, s, o);
        sq += __shfl_xor_sync(0xffffffffu, sq, o);
    }
    if (lane == 0) {
        float mu = s * (1.f / 256.f);
        float var = sq * (1.f / 256.f) - mu * mu;
        mean[warp] = mu;
        rstd[warp] = rsqrtf(var + 1e-5f);
    }
}

// ---------------------------------------------------------------------------
// Window attention on tensor cores (validated in R5)
// ---------------------------------------------------------------------------
constexpr int QS_STRIDE = 132;
constexpr int VS_STRIDE = 136;
constexpr int PS_STRIDE = 68;
constexpr int ATTN_SMEM = (2 * 64 * QS_STRIDE + 64 * VS_STRIDE + 64 * PS_STRIDE) * 4;

__launch_bounds__(256)
__global__ void attn_k(const float* __restrict__ q, const float* __restrict__ k,
                       const float* __restrict__ v, float* __restrict__ out) {
    extern __shared__ float sm[];
    float* Qs = sm;
    float* Ks = Qs + 64 * QS_STRIDE;
    float* Vs = Ks + 64 * QS_STRIDE;
    float* Ps = Vs + 64 * VS_STRIDE;

    const int widx = blockIdx.x;
    const int b = widx >> 6, wh = (widx >> 3) & 7, ww = widx & 7;
    const int tid  = threadIdx.x;
    const int lane = tid & 31, w = tid >> 5;
    const int wm = w & 3, wn = w >> 2;
    const int lr = lane >> 2, lc = lane & 3;

    auto grow = [&](int i) -> size_t {
        return ((size_t)(b * Nn + (wh * 7 + i / 7) * 56 + ww * 7 + (i % 7))) * 128;
    };

    for (int e = tid; e < 49 * 32; e += 256) {
        int i = e >> 5, c4 = (e & 31) * 4;
        size_t g = grow(i) + c4;
        float4 a  = *(const float4*)(q + g);
        float4 kk = *(const float4*)(k + g);
        float4 vv = *(const float4*)(v + g);
        *(float4*)(Qs + i * QS_STRIDE + c4) =
            make_float4(tf32r(a.x), tf32r(a.y), tf32r(a.z), tf32r(a.w));
        *(float4*)(Ks + i * QS_STRIDE + c4) =
            make_float4(tf32r(kk.x), tf32r(kk.y), tf32r(kk.z), tf32r(kk.w));
        *(float4*)(Vs + i * VS_STRIDE + c4) =
            make_float4(tf32r(vv.x), tf32r(vv.y), tf32r(vv.z), tf32r(vv.w));
    }
    for (int e = tid; e < 15 * QS_STRIDE; e += 256) {
        Qs[49 * QS_STRIDE + e] = 0.f;
        Ks[49 * QS_STRIDE + e] = 0.f;
    }
    for (int e = tid; e < 15 * VS_STRIDE; e += 256) Vs[49 * VS_STRIDE + e] = 0.f;
    __syncthreads();

    float acc[4][4] = {};
    #pragma unroll
    for (int k8 = 0; k8 < 16; k8++) {
        int r = wm * 16 + lr, c = k8 * 8 + lc;
        float4 a = make_float4(Qs[r * QS_STRIDE + c],     Qs[(r + 8) * QS_STRIDE + c],
                               Qs[r * QS_STRIDE + c + 4], Qs[(r + 8) * QS_STRIDE + c + 4]);
        #pragma unroll
        for (int u = 0; u < 4; u++) {
            int n = wn * 32 + u * 8 + lr;
            float2 bf = make_float2(Ks[n * QS_STRIDE + c], Ks[n * QS_STRIDE + c + 4]);
            mma_tf32(acc[u], a, bf);
        }
    }
    #pragma unroll
    for (int u = 0; u < 4; u++) {
        int r = wm * 16 + lr, n = wn * 32 + u * 8 + lc * 2;
        *(float2*)(Ps + r * PS_STRIDE + n)       = make_float2(acc[u][0], acc[u][1]);
        *(float2*)(Ps + (r + 8) * PS_STRIDE + n) = make_float2(acc[u][2], acc[u][3]);
    }
    __syncthreads();

    if (tid < 49) {
        const float scale = 0.08838834764831845f;
        float* r = Ps + tid * PS_STRIDE;
        float mx = r[0];
        #pragma unroll 7
        for (int j = 1; j < 49; j++) mx = fmaxf(mx, r[j]);
        float s = 0.f;
        #pragma unroll 7
        for (int j = 0; j < 49; j++) { float e = expf((r[j] - mx) * scale); r[j] = e; s += e; }
        float inv = 1.f / s;
        #pragma unroll 7
        for (int j = 0; j < 49; j++) r[j] = tf32r(r[j] * inv);
        #pragma unroll
        for (int j = 49; j < 64; j++) r[j] = 0.f;
    }
    __syncthreads();

    float o[8][4] = {};
    #pragma unroll
    for (int k8 = 0; k8 < 8; k8++) {
        int r = wm * 16 + lr, c = k8 * 8 + lc;
        float4 a = make_float4(Ps[r * PS_STRIDE + c],     Ps[(r + 8) * PS_STRIDE + c],
                               Ps[r * PS_STRIDE + c + 4], Ps[(r + 8) * PS_STRIDE + c + 4]);
        #pragma unroll
        for (int u = 0; u < 8; u++) {
            int n = wn * 64 + u * 8 + lr;
            float2 bf = make_float2(Vs[c * VS_STRIDE + n], Vs[(c + 4) * VS_STRIDE + n]);
            mma_tf32(o[u], a, bf);
        }
    }
    int r0 = wm * 16 + lr;
    #pragma unroll
    for (int u = 0; u < 8; u++) {
        int n = wn * 64 + u * 8 + lc * 2;
        if (r0 < 49)     *(float2*)(out + grow(r0) + n)     = make_float2(o[u][0], o[u][1]);
        if (r0 + 8 < 49) *(float2*)(out + grow(r0 + 8) + n) = make_float2(o[u][2], o[u][3]);
    }
}

// ---------------------------------------------------------------------------
// BatchNorm pieces
// ---------------------------------------------------------------------------
__global__ void bn_stats_k(const float* __restrict__ x, float* __restrict__ part) {
    int c = threadIdx.x & 127;
    int half = threadIdx.x >> 7;
    float s = 0.f, sq = 0.f;
    int rbeg = blockIdx.x * 128 + half;
    int rend = blockIdx.x * 128 + 128;
    for (int r = rbeg; r < rend; r += 2) {
        float vv = x[(size_t)r * 128 + c];
        s += vv; sq += vv * vv;
    }
    __shared__ float sh[512];
    sh[threadIdx.x] = s;
    sh[256 + threadIdx.x] = sq;
    __syncthreads();
    if (half == 0) {
        part[blockIdx.x * 256 + c]       = sh[c] + sh[128 + c];
        part[blockIdx.x * 256 + 128 + c] = sh[256 + c] + sh[256 + 128 + c];
    }
}

// read-only: stats of relu(bn1(x))
__global__ void bn2_stats_k(const float* __restrict__ x,
                            const float* __restrict__ s1, const float* __restrict__ h1,
                            float* __restrict__ part) {
    int c = threadIdx.x & 127;
    int half = threadIdx.x >> 7;
    float sc = s1[c], sh_ = h1[c];
    float s = 0.f, sq = 0.f;
    int rbeg = blockIdx.x * 128 + half;
    int rend = blockIdx.x * 128 + 128;
    for (int r = rbeg; r < rend; r += 2) {
        float vv = fmaxf(x[(size_t)r * 128 + c] * sc + sh_, 0.f);
        s += vv; sq += vv * vv;
    }
    __shared__ float shm[512];
    shm[threadIdx.x] = s;
    shm[256 + threadIdx.x] = sq;
    __syncthreads();
    if (half == 0) {
        part[blockIdx.x * 256 + c]       = shm[c] + shm[128 + c];
        part[blockIdx.x * 256 + 128 + c] = shm[256 + c] + shm[256 + 128 + c];
    }
}

__global__ void bn_reduce_k(const float* __restrict__ part, const float* __restrict__ g,
                            const float* __restrict__ beta, float* __restrict__ scale,
                            float* __restrict__ shift) {
    int c = threadIdx.x;
    float s = 0.f, sq = 0.f;
    for (int i = 0; i < 784; i++) {
        s  += part[i * 256 + c];
        sq += part[i * 256 + 128 + c];
    }
    float mean = s / (float)Mm;
    float var  = sq / (float)Mm - mean * mean;
    float sc_  = g[c] * rsqrtf(var + 1e-5f);
    scale[c] = sc_;
    shift[c] = beta[c] - mean * sc_;
}

// ---------------------------------------------------------------------------
// Host launch
// ---------------------------------------------------------------------------
static float* symaddr(const void* devsym) {
    void* p = nullptr;
    cudaGetSymbolAddress(&p, devsym);
    return (float*)p;
}

extern "C" void kernel_launch(void* const* d_in, const int* in_sizes, int n_in,
                              void* d_out, int out_size) {
    const float* x     = (const float*)d_in[0];
    const float* fc1_w = (const float*)d_in[1];
    const float* fc1_b = (const float*)d_in[2];
    const float* fc2_w = (const float*)d_in[3];
    const float* fc2_b = (const float*)d_in[4];
    const float* fc3_w = (const float*)d_in[5];
    const float* fc3_b = (const float*)d_in[6];
    const float* fc4_w = (const float*)d_in[7];
    const float* fc4_b = (const float*)d_in[8];
    const float* fc5_w = (const float*)d_in[9];
    const float* fc5_b = (const float*)d_in[10];
    const float* fc6_w = (const float*)d_in[11];
    const float* fc6_b = (const float*)d_in[12];
    const float* ln_w  = (const float*)d_in[13];
    const float* ln_b  = (const float*)d_in[14];
    const float* q_w   = (const float*)d_in[15];
    const float* q_b   = (const float*)d_in[16];
    const float* k_w   = (const float*)d_in[17];
    const float* k_b   = (const float*)d_in[18];
    const float* v_w   = (const float*)d_in[19];
    const float* v_b   = (const float*)d_in[20];
    const float* bn1_g = (const float*)d_in[21];
    const float* bn1_b = (const float*)d_in[22];
    const float* bn2_g = (const float*)d_in[23];
    const float* bn2_b = (const float*)d_in[24];

    float* t0   = symaddr(g_t0);
    float* t1   = symaddr(g_t1);
    float* x1a  = symaddr(g_x1a);
    float* x2a  = symaddr(g_x2a);
    float* qb   = symaddr(g_q);
    float* kb   = symaddr(g_k);
    float* vb   = symaddr(g_v);
    float* att  = symaddr(g_att);
    float* stat = symaddr(g_stats);
    float* mean = stat;
    float* rstd = stat + Mm;
    float* part = symaddr(g_part);
    float* s1   = symaddr(g_s1);
    float* h1   = symaddr(g_h1);
    float* s2   = symaddr(g_s2);
    float* h2   = symaddr(g_h2);

    const int gridR = Bb * 56;
    const int gridG = Mm / 128;          // 784

    auto setsm = [](const void* f) {
        cudaFuncSetAttribute(f, cudaFuncAttributeMaxDynamicSharedMemorySize, SM_ALL);
    };
    setsm((const void*)gemm_k<128, EPI_GELU, 0, false, false>);
    setsm((const void*)gemm_k<128, EPI_RES,  0, false, false>);
    setsm((const void*)gemm_k<128, EPI_BIAS, 0, true,  true >);
    setsm((const void*)gemm_k<256, EPI_RES,  2, false, false>);
    setsm((const void*)gemm_k<256, EPI_BIAS, 3, false, false>);
    cudaFuncSetAttribute(attn_k, cudaFuncAttributeMaxDynamicSharedMemorySize, ATTN_SMEM);

    #define GEMM_ARGS(A0,A1,B,bias,res,q0,q1,q2,q3,C) \
        A0, A1, B, nullptr, nullptr, bias, nullptr, nullptr, res, q0, q1, q2, q3, C, nullptr, nullptr

    // Branch 1
    roll_k<0><<<gridR, 256>>>(x, t0);
    gemm_k<128, EPI_GELU, 0, false, false><<<gridG, 256, SM_ALL>>>(
        GEMM_ARGS(t0, nullptr, fc1_w, fc1_b, nullptr, nullptr, nullptr, nullptr, nullptr, t1));
    roll_k<1><<<gridR, 256>>>(t1, t0);
    gemm_k<128, EPI_RES, 0, false, false><<<gridG, 256, SM_ALL>>>(
        GEMM_ARGS(t0, nullptr, fc2_w, fc2_b, x, nullptr, nullptr, nullptr, nullptr, x1a));

    // Branch 2
    roll_k<2><<<gridR, 256>>>(x, t0);
    gemm_k<128, EPI_GELU, 0, false, false><<<gridG, 256, SM_ALL>>>(
        GEMM_ARGS(t0, nullptr, fc3_w, fc3_b, nullptr, nullptr, nullptr, nullptr, nullptr, t1));
    roll_k<0><<<gridR, 256>>>(t1, t0);
    gemm_k<128, EPI_RES, 0, false, false><<<gridG, 256, SM_ALL>>>(
        GEMM_ARGS(t0, nullptr, fc4_w, fc4_b, x, nullptr, nullptr, nullptr, nullptr, x2a));

    // LN stats + fc5 (LN folded into A-gather) + residual -> t0
    ln_stats_k<<<Mm / 8, 256>>>(x1a, x2a, mean, rstd);
    gemm_k<256, EPI_RES, 2, false, false><<<gridG, 256, SM_ALL>>>(
        x1a, x2a, fc5_w, nullptr, nullptr, fc5_b, nullptr, nullptr, x,
        mean, rstd, ln_w, ln_b, t0, nullptr, nullptr);

    // q/k/v in one launch (grid.y selects weight/bias/output)
    gemm_k<128, EPI_BIAS, 0, true, true><<<dim3(gridG, 3), 256, SM_ALL>>>(
        x, nullptr, q_w, k_w, v_w, q_b, k_b, v_b, nullptr,
        nullptr, nullptr, nullptr, nullptr, qb, kb, vb);

    // Window attention (tensor cores)
    attn_k<<<2048, 256, ATTN_SMEM>>>(qb, kb, vb, att);

    // BN1 stats -> reduce -> BN2 stats (read-only, relu(bn1) on the fly) -> reduce
    bn_stats_k<<<784, 256>>>(att, part);
    bn_reduce_k<<<1, 128>>>(part, bn1_g, bn1_b, s1, h1);
    bn2_stats_k<<<784, 256>>>(att, s1, h1, part);
    bn_reduce_k<<<1, 128>>>(part, bn2_g, bn2_b, s2, h2);

    // Final: out = [x1 | relu(bn1(att))*bn2] @ fc6 + b  (full fold in A-gather)
    gemm_k<256, EPI_BIAS, 3, false, false><<<gridG, 256, SM_ALL>>>(
        t0, att, fc6_w, nullptr, nullptr, fc6_b, nullptr, nullptr, nullptr,
        s1, h1, s2, h2, (float*)d_out, nullptr, nullptr);
}

// round 13
// speedup vs baseline: 1.2287x; 1.0509x over previous
#include <cuda_runtime.h>
#include <math.h>
#include <stdint.h>

constexpr int Bb = 32;
constexpr int Hh = 56;
constexpr int Ww = 56;
constexpr int Cc = 128;
constexpr int Nn = Hh * Ww;              // 3136
constexpr int Mm = Bb * Nn;              // 100352
constexpr size_t MC = (size_t)Mm * Cc;

__device__ float g_t0[MC];
__device__ float g_t1[MC];
__device__ float g_x1a[MC];
__device__ float g_x2a[MC];
__device__ float g_q[MC];
__device__ float g_k[MC];
__device__ float g_v[MC];
__device__ float g_att[MC];
__device__ float g_stats[2 * Mm];        // LN mean | rstd
__device__ float g_part[784 * 256];
__device__ float g_s1[Cc];
__device__ float g_h1[Cc];
__device__ float g_s2[Cc];
__device__ float g_h2[Cc];

__device__ __forceinline__ float tf32r(float x) {
    uint32_t u;
    asm("cvt.rna.tf32.f32 %0, %1;" : "=r"(u) : "f"(x));
    return __uint_as_float(u);
}

__device__ __forceinline__ void mma_tf32(float* c, const float4& a, const float2& b) {
    asm volatile(
        "mma.sync.aligned.m16n8k8.row.col.f32.tf32.tf32.f32 "
        "{%0,%1,%2,%3}, {%4,%5,%6,%7}, {%8,%9}, {%0,%1,%2,%3};"
        : "+f"(c[0]), "+f"(c[1]), "+f"(c[2]), "+f"(c[3])
        : "r"(__float_as_uint(a.x)), "r"(__float_as_uint(a.y)),
          "r"(__float_as_uint(a.z)), "r"(__float_as_uint(a.w)),
          "r"(__float_as_uint(b.x)), "r"(__float_as_uint(b.y)));
}

// ---------------------------------------------------------------------------
// Per-channel roll. MODE 0: H,+c  1: W,+c  2: W,-c
// ---------------------------------------------------------------------------
template <int MODE>
__launch_bounds__(256)
__global__ void roll_k(const float* __restrict__ in, float* __restrict__ out) {
    __shared__ float tile[56 * 128];
    const int tid = threadIdx.x;
    const int b = blockIdx.x / 56;
    const int f = blockIdx.x % 56;
    const size_t base   = (MODE == 0) ? ((size_t)b * Nn + f) * 128
                                      : ((size_t)(b * 56 + f) * 56) * 128;
    const int    stride = (MODE == 0) ? 56 * 128 : 128;

    #pragma unroll
    for (int e = tid; e < 56 * 32; e += 256) {
        int rowi = e >> 5, c4 = e & 31;
        ((float4*)tile)[rowi * 32 + c4] =
            *(const float4*)(in + base + (size_t)rowi * stride + c4 * 4);
    }
    __syncthreads();

    #pragma unroll
    for (int e = tid; e < 56 * 128; e += 256) {
        int pos = e >> 7, c = e & 127;
        int cm = c % 56;
        int src = (MODE == 2) ? pos + cm : pos - cm;
        if (src < 0) src += 56;
        if (src >= 56) src -= 56;
        out[base + (size_t)pos * stride + c] = tile[src * 128 + c];
    }
}

// ---------------------------------------------------------------------------
// TF32 GEMM (R9/R12 measured-best config). Coalesced LDG.128 -> XOR-swizzled
// smem A (conflict-free both sides). Register prefetch distance 2, ONE barrier
// per slice. B resident fragment-order smem (64 KB chunk; K=256 swaps once).
// AMODE: 0 plain A[M,K]; 1 split+per-col affine on A1; 2 split+LN fold;
//        3 split+relu(bn1)*bn2 fold. QKV: grid.y selects B/bias/C.
// ---------------------------------------------------------------------------
enum { EPI_GELU = 0, EPI_BIAS = 1, EPI_RES = 2 };
constexpr int SM_ALL = 16 * 16 * 32 * 8 + 2 * 128 * 32 * 4;   // 64KB B + 32KB A

template <int K, int EPI, int AMODE, bool BT, bool QKV>
__launch_bounds__(256, 2)
__global__ void gemm_k(const float* __restrict__ A0, const float* __restrict__ A1,
                       const float* __restrict__ B0, const float* __restrict__ B1,
                       const float* __restrict__ B2,
                       const float* __restrict__ bias0, const float* __restrict__ bias1,
                       const float* __restrict__ bias2,
                       const float* __restrict__ res,
                       const float* __restrict__ p0, const float* __restrict__ p1,
                       const float* __restrict__ p2, const float* __restrict__ p3,
                       float* __restrict__ C0, float* __restrict__ C1,
                       float* __restrict__ C2) {
    extern __shared__ float smem[];
    float2* Bs = (float2*)smem;                 // [16 k8][16 nt][32 lane]
    float*  As = smem + 16384;                  // 2 bufs x 128 rows x 32 (swizzled)

    const float* Bm = B0;
    const float* bias = bias0;
    float* Cm = C0;
    if (QKV) {
        int y = blockIdx.y;
        if (y == 1) { Bm = B1; bias = bias1; Cm = C1; }
        else if (y == 2) { Bm = B2; bias = bias2; Cm = C2; }
    }

    const int tid  = threadIdx.x;
    const int lane = tid & 31;
    const int wid  = tid >> 5;
    const int wm   = wid & 3;
    const int wn   = wid >> 2;
    const int row0 = blockIdx.x * 128;
    const int lr   = lane >> 2;
    const int lc   = lane & 3;

    auto loadB = [&](int ko) {
        for (int frag = wid; frag < 256; frag += 8) {
            int k8l = frag >> 4, nt = frag & 15;
            int kk = ko + k8l * 8 + lc, n = nt * 8 + lr;
            float b0v, b1v;
            if (BT) { b0v = Bm[(size_t)n * K + kk];   b1v = Bm[(size_t)n * K + kk + 4]; }
            else    { b0v = Bm[(size_t)kk * 128 + n]; b1v = Bm[(size_t)(kk + 4) * 128 + n]; }
            Bs[frag * 32 + lane] = make_float2(tf32r(b0v), tf32r(b1v));
        }
    };

    // ---- A producer: thread loads rows (tid>>3)+{0,32,64,96}, c4 block tid&7
    const int arow = tid >> 3;
    const int ac4  = tid & 7;
    float mrow[4], rrow[4];
    if (AMODE == 2) {
        #pragma unroll
        for (int i = 0; i < 4; i++) {
            int gr = row0 + arow + i * 32;
            mrow[i] = p0[gr];
            rrow[i] = p1[gr];
        }
    }

    auto fetch4 = [&](int i, int c) -> float4 {
        int gr = row0 + arow + i * 32;
        float4 v;
        if (AMODE == 0) {
            v = *(const float4*)(A0 + (size_t)gr * K + c);
        } else {
            v = (c < 128) ? *(const float4*)(A0 + (size_t)gr * 128 + c)
                          : *(const float4*)(A1 + (size_t)gr * 128 + (c - 128));
            if (AMODE == 1) {
                if (c >= 128) {
                    float4 s = *(const float4*)(p0 + c - 128);
                    float4 h = *(const float4*)(p1 + c - 128);
                    v.x = v.x * s.x + h.x; v.y = v.y * s.y + h.y;
                    v.z = v.z * s.z + h.z; v.w = v.w * s.w + h.w;
                }
            } else if (AMODE == 2) {
                float4 g = *(const float4*)(p2 + c);
                float4 bb = *(const float4*)(p3 + c);
                float mn = mrow[i], rs = rrow[i];
                v.x = (v.x - mn) * rs * g.x + bb.x;
                v.y = (v.y - mn) * rs * g.y + bb.y;
                v.z = (v.z - mn) * rs * g.z + bb.z;
                v.w = (v.w - mn) * rs * g.w + bb.w;
            } else {            // AMODE 3: relu(bn1)*bn2 fold on A1
                if (c >= 128) {
                    float4 sa = *(const float4*)(p0 + c - 128);
                    float4 ha = *(const float4*)(p1 + c - 128);
                    float4 sb = *(const float4*)(p2 + c - 128);
                    float4 hb = *(const float4*)(p3 + c - 128);
                    v.x = fmaxf(v.x * sa.x + ha.x, 0.f) * sb.x + hb.x;
                    v.y = fmaxf(v.y * sa.y + ha.y, 0.f) * sb.y + hb.y;
                    v.z = fmaxf(v.z * sa.z + ha.z, 0.f) * sb.z + hb.z;
                    v.w = fmaxf(v.w * sa.w + ha.w, 0.f) * sb.w + hb.w;
                }
            }
        }
        return make_float4(tf32r(v.x), tf32r(v.y), tf32r(v.z), tf32r(v.w));
    };

    float4 pa[2][4];
    auto gather = [&](int kc, int set) {
        int c = kc + ac4 * 4;
        #pragma unroll
        for (int i = 0; i < 4; i++) pa[set][i] = fetch4(i, c);
    };

    loadB(0);
    gather(0, 0);
    gather(32, 1);

    float acc[2][8][4] = {};
    constexpr int NS = K / 32;

    #pragma unroll
    for (int s = 0; s < NS; s++) {
        const int set = s & 1;
        const int bo = set * 4096;
        // STS swizzled: addr(row,c4) = row*32 + 4*(c4 ^ (row&7))
        #pragma unroll
        for (int i = 0; i < 4; i++) {
            int row = arow + i * 32;
            *(float4*)(As + bo + row * 32 + 4 * (ac4 ^ (row & 7))) = pa[set][i];
        }
        __syncthreads();
        if (K > 128 && s == 4) {            // swap B chunk (all warps past mma(3))
            loadB(128);
            __syncthreads();
        }
        if (s + 2 < NS) gather((s + 2) * 32, set);
        const int kb = (s & 3) * 4;
        #pragma unroll
        for (int k8 = 0; k8 < 4; k8++) {
            float4 av[2];
            #pragma unroll
            for (int mt2 = 0; mt2 < 2; mt2++) {
                int r = wm * 32 + mt2 * 16 + lr;
                int s0 = 4 * ((2 * k8) ^ lr) + lc;
                int s1 = 4 * ((2 * k8 + 1) ^ lr) + lc;
                const float* b1p = As + bo + r * 32;
                const float* b2p = As + bo + (r + 8) * 32;
                av[mt2] = make_float4(b1p[s0], b2p[s0], b1p[s1], b2p[s1]);
            }
            #pragma unroll
            for (int u = 0; u < 8; u++) {
                float2 b = Bs[((kb + k8) * 16 + wn * 8 + u) * 32 + lane];
                mma_tf32(acc[0][u], av[0], b);
                mma_tf32(acc[1][u], av[1], b);
            }
        }
    }

    const int ec = lc * 2;
    #pragma unroll
    for (int t = 0; t < 2; t++) {
        int m0 = row0 + wm * 32 + t * 16 + lr;
        #pragma unroll
        for (int u = 0; u < 8; u++) {
            int n = wn * 64 + u * 8 + ec;
            float b0 = bias[n], b1 = bias[n + 1];
            float v0 = acc[t][u][0] + b0;
            float v1 = acc[t][u][1] + b1;
            float v2 = acc[t][u][2] + b0;
            float v3 = acc[t][u][3] + b1;
            if (EPI == EPI_GELU) {
                v0 = 0.5f * v0 * (1.0f + erff(v0 * 0.70710678f));
                v1 = 0.5f * v1 * (1.0f + erff(v1 * 0.70710678f));
                v2 = 0.5f * v2 * (1.0f + erff(v2 * 0.70710678f));
                v3 = 0.5f * v3 * (1.0f + erff(v3 * 0.70710678f));
            } else if (EPI == EPI_RES) {
                float2 r0 = *(const float2*)(res + (size_t)m0 * 128 + n);
                float2 rr = *(const float2*)(res + (size_t)(m0 + 8) * 128 + n);
                v0 += r0.x; v1 += r0.y; v2 += rr.x; v3 += rr.y;
            }
            *(float2*)(Cm + (size_t)m0 * 128 + n)       = make_float2(v0, v1);
            *(float2*)(Cm + (size_t)(m0 + 8) * 128 + n) = make_float2(v2, v3);
        }
    }
}

// ---------------------------------------------------------------------------
// LayerNorm stats only: per-token mean & rstd over the 256-wide concat
// ---------------------------------------------------------------------------
__global__ void ln_stats_k(const float* __restrict__ x1a, const float* __restrict__ x2a,
                           float* __restrict__ mean, float* __restrict__ rstd) {
    int warp = (blockIdx.x * blockDim.x + threadIdx.x) >> 5;
    int lane = threadIdx.x & 31;
    if (warp >= Mm) return;
    float s = 0.f, sq = 0.f;
    #pragma unroll
    for (int kq = 0; kq < 4; kq++) {
        float a = x1a[(size_t)warp * 128 + lane + 32 * kq];
        float b = x2a[(size_t)warp * 128 + lane + 32 * kq];
        s += a + b; sq += a * a + b * b;
    }
    #pragma unroll
    for (int o = 16; o > 0; o >>= 1) {
        s  += __shfl_xor_sync(0xffffffffu, s, o);
        sq += __shfl_xor_sync(0xffffffffu, sq, o);
    }
    if (lane == 0) {
        float mu = s * (1.f / 256.f);
        float var = sq * (1.f / 256.f) - mu * mu;
        mean[warp] = mu;
        rstd[warp] = rsqrtf(var + 1e-5f);
    }
}

// ---------------------------------------------------------------------------
// Window attention on tensor cores. Smem squeezed to 98 KB (2 CTAs/SM):
// Ps aliases Qs (Q dead after S-mma; extra barrier added), VS_STRIDE=128
// (store/read patterns conflict-free for any stride), Q/K pad zeroing
// dropped (garbage reaches only discarded S rows / softmax-overwritten cols).
// ---------------------------------------------------------------------------
constexpr int QS_STRIDE = 132;
constexpr int VS_STRIDE = 128;
constexpr int PS_STRIDE = 68;
constexpr int ATTN_SMEM = (2 * 64 * QS_STRIDE + 64 * VS_STRIDE) * 4;   // 98 KB

__launch_bounds__(256)
__global__ void attn_k(const float* __restrict__ q, const float* __restrict__ k,
                       const float* __restrict__ v, float* __restrict__ out) {
    extern __shared__ float sm[];
    float* Qs = sm;
    float* Ks = Qs + 64 * QS_STRIDE;
    float* Vs = Ks + 64 * QS_STRIDE;
    float* Ps = Qs;                       // alias: Q dead after S-mma

    const int widx = blockIdx.x;
    const int b = widx >> 6, wh = (widx >> 3) & 7, ww = widx & 7;
    const int tid  = threadIdx.x;
    const int lane = tid & 31, w = tid >> 5;
    const int wm = w & 3, wn = w >> 2;
    const int lr = lane >> 2, lc = lane & 3;

    auto grow = [&](int i) -> size_t {
        return ((size_t)(b * Nn + (wh * 7 + i / 7) * 56 + ww * 7 + (i % 7))) * 128;
    };

    for (int e = tid; e < 49 * 32; e += 256) {
        int i = e >> 5, c4 = (e & 31) * 4;
        size_t g = grow(i) + c4;
        float4 a  = *(const float4*)(q + g);
        float4 kk = *(const float4*)(k + g);
        float4 vv = *(const float4*)(v + g);
        *(float4*)(Qs + i * QS_STRIDE + c4) =
            make_float4(tf32r(a.x), tf32r(a.y), tf32r(a.z), tf32r(a.w));
        *(float4*)(Ks + i * QS_STRIDE + c4) =
            make_float4(tf32r(kk.x), tf32r(kk.y), tf32r(kk.z), tf32r(kk.w));
        *(float4*)(Vs + i * VS_STRIDE + c4) =
            make_float4(tf32r(vv.x), tf32r(vv.y), tf32r(vv.z), tf32r(vv.w));
    }
    // zero V pad rows only (K-dim of PV: 0 * garbage-NaN hazard)
    for (int e = tid; e < 15 * VS_STRIDE; e += 256) Vs[49 * VS_STRIDE + e] = 0.f;
    __syncthreads();

    // S = Q K^T (warp tile m16 x n32)
    float acc[4][4] = {};
    #pragma unroll
    for (int k8 = 0; k8 < 16; k8++) {
        int r = wm * 16 + lr, c = k8 * 8 + lc;
        float4 a = make_float4(Qs[r * QS_STRIDE + c],     Qs[(r + 8) * QS_STRIDE + c],
                               Qs[r * QS_STRIDE + c + 4], Qs[(r + 8) * QS_STRIDE + c + 4]);
        #pragma unroll
        for (int u = 0; u < 4; u++) {
            int n = wn * 32 + u * 8 + lr;
            float2 bf = make_float2(Ks[n * QS_STRIDE + c], Ks[n * QS_STRIDE + c + 4]);
            mma_tf32(acc[u], a, bf);
        }
    }
    __syncthreads();                       // all warps done reading Qs before Ps writes
    #pragma unroll
    for (int u = 0; u < 4; u++) {
        int r = wm * 16 + lr, n = wn * 32 + u * 8 + lc * 2;
        *(float2*)(Ps + r * PS_STRIDE + n)       = make_float2(acc[u][0], acc[u][1]);
        *(float2*)(Ps + (r + 8) * PS_STRIDE + n) = make_float2(acc[u][2], acc[u][3]);
    }
    __syncthreads();

    if (tid < 49) {
        const float scale = 0.08838834764831845f;
        float* r = Ps + tid * PS_STRIDE;
        float mx = r[0];
        #pragma unroll 7
        for (int j = 1; j < 49; j++) mx = fmaxf(mx, r[j]);
        float s = 0.f;
        #pragma unroll 7
        for (int j = 0; j < 49; j++) { float e = expf((r[j] - mx) * scale); r[j] = e; s += e; }
        float inv = 1.f / s;
        #pragma unroll 7
        for (int j = 0; j < 49; j++) r[j] = tf32r(r[j] * inv);
        #pragma unroll
        for (int j = 49; j < 64; j++) r[j] = 0.f;
    }
    __syncthreads();

    // O = P V (warp tile m16 x n64)
    float o[8][4] = {};
    #pragma unroll
    for (int k8 = 0; k8 < 8; k8++) {
        int r = wm * 16 + lr, c = k8 * 8 + lc;
        float4 a = make_float4(Ps[r * PS_STRIDE + c],     Ps[(r + 8) * PS_STRIDE + c],
                               Ps[r * PS_STRIDE + c + 4], Ps[(r + 8) * PS_STRIDE + c + 4]);
        #pragma unroll
        for (int u = 0; u < 8; u++) {
            int n = wn * 64 + u * 8 + lr;
            float2 bf = make_float2(Vs[c * VS_STRIDE + n], Vs[(c + 4) * VS_STRIDE + n]);
            mma_tf32(o[u], a, bf);
        }
    }
    int r0 = wm * 16 + lr;
    #pragma unroll
    for (int u = 0; u < 8; u++) {
        int n = wn * 64 + u * 8 + lc * 2;
        if (r0 < 49)     *(float2*)(out + grow(r0) + n)     = make_float2(o[u][0], o[u][1]);
        if (r0 + 8 < 49) *(float2*)(out + grow(r0 + 8) + n) = make_float2(o[u][2], o[u][3]);
    }
}

// ---------------------------------------------------------------------------
// BatchNorm pieces
// ---------------------------------------------------------------------------
__global__ void bn_stats_k(const float* __restrict__ x, float* __restrict__ part) {
    int c = threadIdx.x & 127;
    int half = threadIdx.x >> 7;
    float s = 0.f, sq = 0.f;
    int rbeg = blockIdx.x * 128 + half;
    int rend = blockIdx.x * 128 + 128;
    for (int r = rbeg; r < rend; r += 2) {
        float vv = x[(size_t)r * 128 + c];
        s += vv; sq += vv * vv;
    }
    __shared__ float sh[512];
    sh[threadIdx.x] = s;
    sh[256 + threadIdx.x] = sq;
    __syncthreads();
    if (half == 0) {
        part[blockIdx.x * 256 + c]       = sh[c] + sh[128 + c];
        part[blockIdx.x * 256 + 128 + c] = sh[256 + c] + sh[256 + 128 + c];
    }
}

// read-only: stats of relu(bn1(x))
__global__ void bn2_stats_k(const float* __restrict__ x,
                            const float* __restrict__ s1, const float* __restrict__ h1,
                            float* __restrict__ part) {
    int c = threadIdx.x & 127;
    int half = threadIdx.x >> 7;
    float sc = s1[c], sh_ = h1[c];
    float s = 0.f, sq = 0.f;
    int rbeg = blockIdx.x * 128 + half;
    int rend = blockIdx.x * 128 + 128;
    for (int r = rbeg; r < rend; r += 2) {
        float vv = fmaxf(x[(size_t)r * 128 + c] * sc + sh_, 0.f);
        s += vv; sq += vv * vv;
    }
    __shared__ float shm[512];
    shm[threadIdx.x] = s;
    shm[256 + threadIdx.x] = sq;
    __syncthreads();
    if (half == 0) {
        part[blockIdx.x * 256 + c]       = shm[c] + shm[128 + c];
        part[blockIdx.x * 256 + 128 + c] = shm[256 + c] + shm[256 + 128 + c];
    }
}

__global__ void bn_reduce_k(const float* __restrict__ part, const float* __restrict__ g,
                            const float* __restrict__ beta, float* __restrict__ scale,
                            float* __restrict__ shift) {
    int c = threadIdx.x;
    float s = 0.f, sq = 0.f;
    for (int i = 0; i < 784; i++) {
        s  += part[i * 256 + c];
        sq += part[i * 256 + 128 + c];
    }
    float mean = s / (float)Mm;
    float var  = sq / (float)Mm - mean * mean;
    float sc_  = g[c] * rsqrtf(var + 1e-5f);
    scale[c] = sc_;
    shift[c] = beta[c] - mean * sc_;
}

// ---------------------------------------------------------------------------
// Host launch
// ---------------------------------------------------------------------------
static float* symaddr(const void* devsym) {
    void* p = nullptr;
    cudaGetSymbolAddress(&p, devsym);
    return (float*)p;
}

extern "C" void kernel_launch(void* const* d_in, const int* in_sizes, int n_in,
                              void* d_out, int out_size) {
    const float* x     = (const float*)d_in[0];
    const float* fc1_w = (const float*)d_in[1];
    const float* fc1_b = (const float*)d_in[2];
    const float* fc2_w = (const float*)d_in[3];
    const float* fc2_b = (const float*)d_in[4];
    const float* fc3_w = (const float*)d_in[5];
    const float* fc3_b = (const float*)d_in[6];
    const float* fc4_w = (const float*)d_in[7];
    const float* fc4_b = (const float*)d_in[8];
    const float* fc5_w = (const float*)d_in[9];
    const float* fc5_b = (const float*)d_in[10];
    const float* fc6_w = (const float*)d_in[11];
    const float* fc6_b = (const float*)d_in[12];
    const float* ln_w  = (const float*)d_in[13];
    const float* ln_b  = (const float*)d_in[14];
    const float* q_w   = (const float*)d_in[15];
    const float* q_b   = (const float*)d_in[16];
    const float* k_w   = (const float*)d_in[17];
    const float* k_b   = (const float*)d_in[18];
    const float* v_w   = (const float*)d_in[19];
    const float* v_b   = (const float*)d_in[20];
    const float* bn1_g = (const float*)d_in[21];
    const float* bn1_b = (const float*)d_in[22];
    const float* bn2_g = (const float*)d_in[23];
    const float* bn2_b = (const float*)d_in[24];

    float* t0   = symaddr(g_t0);
    float* t1   = symaddr(g_t1);
    float* x1a  = symaddr(g_x1a);
    float* x2a  = symaddr(g_x2a);
    float* qb   = symaddr(g_q);
    float* kb   = symaddr(g_k);
    float* vb   = symaddr(g_v);
    float* att  = symaddr(g_att);
    float* stat = symaddr(g_stats);
    float* mean = stat;
    float* rstd = stat + Mm;
    float* part = symaddr(g_part);
    float* s1   = symaddr(g_s1);
    float* h1   = symaddr(g_h1);
    float* s2   = symaddr(g_s2);
    float* h2   = symaddr(g_h2);

    const int gridR = Bb * 56;
    const int gridG = Mm / 128;          // 784

    auto setsm = [](const void* f) {
        cudaFuncSetAttribute(f, cudaFuncAttributeMaxDynamicSharedMemorySize, SM_ALL);
    };
    setsm((const void*)gemm_k<128, EPI_GELU, 0, false, false>);
    setsm((const void*)gemm_k<128, EPI_RES,  0, false, false>);
    setsm((const void*)gemm_k<128, EPI_BIAS, 0, true,  true >);
    setsm((const void*)gemm_k<256, EPI_RES,  2, false, false>);
    setsm((const void*)gemm_k<256, EPI_BIAS, 3, false, false>);
    cudaFuncSetAttribute(attn_k, cudaFuncAttributeMaxDynamicSharedMemorySize, ATTN_SMEM);

    #define GEMM_ARGS(A0,A1,B,bias,res,q0,q1,q2,q3,C) \
        A0, A1, B, nullptr, nullptr, bias, nullptr, nullptr, res, q0, q1, q2, q3, C, nullptr, nullptr

    // Branch 1
    roll_k<0><<<gridR, 256>>>(x, t0);
    gemm_k<128, EPI_GELU, 0, false, false><<<gridG, 256, SM_ALL>>>(
        GEMM_ARGS(t0, nullptr, fc1_w, fc1_b, nullptr, nullptr, nullptr, nullptr, nullptr, t1));
    roll_k<1><<<gridR, 256>>>(t1, t0);
    gemm_k<128, EPI_RES, 0, false, false><<<gridG, 256, SM_ALL>>>(
        GEMM_ARGS(t0, nullptr, fc2_w, fc2_b, x, nullptr, nullptr, nullptr, nullptr, x1a));

    // Branch 2
    roll_k<2><<<gridR, 256>>>(x, t0);
    gemm_k<128, EPI_GELU, 0, false, false><<<gridG, 256, SM_ALL>>>(
        GEMM_ARGS(t0, nullptr, fc3_w, fc3_b, nullptr, nullptr, nullptr, nullptr, nullptr, t1));
    roll_k<0><<<gridR, 256>>>(t1, t0);
    gemm_k<128, EPI_RES, 0, false, false><<<gridG, 256, SM_ALL>>>(
        GEMM_ARGS(t0, nullptr, fc4_w, fc4_b, x, nullptr, nullptr, nullptr, nullptr, x2a));

    // LN stats + fc5 (LN folded into A-gather) + residual -> t0
    ln_stats_k<<<Mm / 8, 256>>>(x1a, x2a, mean, rstd);
    gemm_k<256, EPI_RES, 2, false, false><<<gridG, 256, SM_ALL>>>(
        x1a, x2a, fc5_w, nullptr, nullptr, fc5_b, nullptr, nullptr, x,
        mean, rstd, ln_w, ln_b, t0, nullptr, nullptr);

    // q/k/v in one launch (grid.y selects weight/bias/output)
    gemm_k<128, EPI_BIAS, 0, true, true><<<dim3(gridG, 3), 256, SM_ALL>>>(
        x, nullptr, q_w, k_w, v_w, q_b, k_b, v_b, nullptr,
        nullptr, nullptr, nullptr, nullptr, qb, kb, vb);

    // Window attention (tensor cores, 2 CTAs/SM)
    attn_k<<<2048, 256, ATTN_SMEM>>>(qb, kb, vb, att);

    // BN1 stats -> reduce -> BN2 stats (read-only, relu(bn1) on the fly) -> reduce
    bn_stats_k<<<784, 256>>>(att, part);
    bn_reduce_k<<<1, 128>>>(part, bn1_g, bn1_b, s1, h1);
    bn2_stats_k<<<784, 256>>>(att, s1, h1, part);
    bn_reduce_k<<<1, 128>>>(part, bn2_g, bn2_b, s2, h2);

    // Final: out = [x1 | relu(bn1(att))*bn2] @ fc6 + b  (full fold in A-gather)
    gemm_k<256, EPI_BIAS, 3, false, false><<<gridG, 256, SM_ALL>>>(
        t0, att, fc6_w, nullptr, nullptr, fc6_b, nullptr, nullptr, nullptr,
        s1, h1, s2, h2, (float*)d_out, nullptr, nullptr);
}

// round 14
// speedup vs baseline: 1.3342x; 1.0858x over previous
#include <cuda_runtime.h>
#include <cuda_fp16.h>
#include <math.h>
#include <stdint.h>

constexpr int Bb = 32;
constexpr int Hh = 56;
constexpr int Ww = 56;
constexpr int Cc = 128;
constexpr int Nn = Hh * Ww;              // 3136
constexpr int Mm = Bb * Nn;              // 100352
constexpr size_t MC = (size_t)Mm * Cc;

__device__ float g_t0[MC];
__device__ float g_t1[MC];
__device__ float g_x1a[MC];
__device__ float g_x2a[MC];
__device__ float g_q[MC];
__device__ float g_k[MC];
__device__ float g_v[MC];
__device__ float g_att[MC];
__device__ float g_stats[2 * Mm];        // LN mean | rstd
__device__ float g_part[784 * 256];
__device__ float g_s1[Cc];
__device__ float g_h1[Cc];
__device__ float g_s2[Cc];
__device__ float g_h2[Cc];

__device__ __forceinline__ float tf32r(float x) {
    uint32_t u;
    asm("cvt.rna.tf32.f32 %0, %1;" : "=r"(u) : "f"(x));
    return __uint_as_float(u);
}

__device__ __forceinline__ void mma_tf32(float* c, const float4& a, const float2& b) {
    asm volatile(
        "mma.sync.aligned.m16n8k8.row.col.f32.tf32.tf32.f32 "
        "{%0,%1,%2,%3}, {%4,%5,%6,%7}, {%8,%9}, {%0,%1,%2,%3};"
        : "+f"(c[0]), "+f"(c[1]), "+f"(c[2]), "+f"(c[3])
        : "r"(__float_as_uint(a.x)), "r"(__float_as_uint(a.y)),
          "r"(__float_as_uint(a.z)), "r"(__float_as_uint(a.w)),
          "r"(__float_as_uint(b.x)), "r"(__float_as_uint(b.y)));
}

__device__ __forceinline__ void mma_f16(float* c, uint32_t a0, uint32_t a1,
                                        uint32_t a2, uint32_t a3,
                                        uint32_t b0, uint32_t b1) {
    asm volatile(
        "mma.sync.aligned.m16n8k16.row.col.f32.f16.f16.f32 "
        "{%0,%1,%2,%3}, {%4,%5,%6,%7}, {%8,%9}, {%0,%1,%2,%3};"
        : "+f"(c[0]), "+f"(c[1]), "+f"(c[2]), "+f"(c[3])
        : "r"(a0), "r"(a1), "r"(a2), "r"(a3), "r"(b0), "r"(b1));
}

__device__ __forceinline__ uint32_t pack2(float x, float y) {
    __half2 h = __floats2half2_rn(x, y);
    return *reinterpret_cast<uint32_t*>(&h);
}

// ---------------------------------------------------------------------------
// Per-channel roll. MODE 0: H,+c  1: W,+c  2: W,-c
// ---------------------------------------------------------------------------
template <int MODE>
__launch_bounds__(256)
__global__ void roll_k(const float* __restrict__ in, float* __restrict__ out) {
    __shared__ float tile[56 * 128];
    const int tid = threadIdx.x;
    const int b = blockIdx.x / 56;
    const int f = blockIdx.x % 56;
    const size_t base   = (MODE == 0) ? ((size_t)b * Nn + f) * 128
                                      : ((size_t)(b * 56 + f) * 56) * 128;
    const int    stride = (MODE == 0) ? 56 * 128 : 128;

    #pragma unroll
    for (int e = tid; e < 56 * 32; e += 256) {
        int rowi = e >> 5, c4 = e & 31;
        ((float4*)tile)[rowi * 32 + c4] =
            *(const float4*)(in + base + (size_t)rowi * stride + c4 * 4);
    }
    __syncthreads();

    #pragma unroll
    for (int e = tid; e < 56 * 128; e += 256) {
        int pos = e >> 7, c = e & 127;
        int cm = c % 56;
        int src = (MODE == 2) ? pos + cm : pos - cm;
        if (src < 0) src += 56;
        if (src >= 56) src -= 56;
        out[base + (size_t)pos * stride + c] = tile[src * 128 + c];
    }
}

// ---------------------------------------------------------------------------
// FP16 tensor-core GEMM (m16n8k16, fp32 accum). Block 128x128, 8 warps
// (4m x 2n), warp tile 32x64. A: coalesced LDG.128 -> fp16 XOR-swizzled smem
// (8B groups; STS.64/LDS.32 conflict-free by bank enumeration). B: whole-K
// resident in fragment-order smem (32KB @K=128, 64KB @K=256 -> no swap).
// Register prefetch distance 2, ONE barrier per slice (R9-validated schedule).
// AMODE: 0 plain A[M,K]; 1 split+per-col affine on A1; 2 split+LN fold;
//        3 split+relu(bn1)*bn2 fold. QKV: grid.y selects B/bias/C.
// ---------------------------------------------------------------------------
enum { EPI_GELU = 0, EPI_BIAS = 1, EPI_RES = 2 };
constexpr int SM_ALL = 64 * 1024 + 16 * 1024;   // B(max 64KB) + A(2 x 8KB)

template <int K, int EPI, int AMODE, bool BT, bool QKV>
__launch_bounds__(256, 2)
__global__ void gemm_k(const float* __restrict__ A0, const float* __restrict__ A1,
                       const float* __restrict__ B0, const float* __restrict__ B1,
                       const float* __restrict__ B2,
                       const float* __restrict__ bias0, const float* __restrict__ bias1,
                       const float* __restrict__ bias2,
                       const float* __restrict__ res,
                       const float* __restrict__ p0, const float* __restrict__ p1,
                       const float* __restrict__ p2, const float* __restrict__ p3,
                       float* __restrict__ C0, float* __restrict__ C1,
                       float* __restrict__ C2) {
    extern __shared__ char smemc[];
    uint2* Bs  = (uint2*)smemc;                 // [(K/16)*16 frags][32 lanes]
    char*  Asb = smemc + 65536;                 // 2 bufs x 128 rows x 64 B

    const float* Bm = B0;
    const float* bias = bias0;
    float* Cm = C0;
    if (QKV) {
        int y = blockIdx.y;
        if (y == 1) { Bm = B1; bias = bias1; Cm = C1; }
        else if (y == 2) { Bm = B2; bias = bias2; Cm = C2; }
    }

    const int tid  = threadIdx.x;
    const int lane = tid & 31;
    const int wid  = tid >> 5;
    const int wm   = wid & 3;
    const int wn   = wid >> 2;
    const int row0 = blockIdx.x * 128;
    const int lr   = lane >> 2;
    const int lc   = lane & 3;

    // ---- whole-K B load in m16n8k16 fragment order ----
    auto loadB = [&]() {
        for (int frag = wid; frag < (K / 16) * 16; frag += 8) {
            int kc = frag >> 4, nt = frag & 15;
            int kk = kc * 16 + lc * 2, n = nt * 8 + lr;
            float v0, v1, v2, v3;
            if (BT) {
                const float* p = Bm + (size_t)n * K + kk;
                v0 = p[0]; v1 = p[1]; v2 = p[8]; v3 = p[9];
            } else {
                v0 = Bm[(size_t)kk * 128 + n];
                v1 = Bm[(size_t)(kk + 1) * 128 + n];
                v2 = Bm[(size_t)(kk + 8) * 128 + n];
                v3 = Bm[(size_t)(kk + 9) * 128 + n];
            }
            Bs[frag * 32 + lane] = make_uint2(pack2(v0, v1), pack2(v2, v3));
        }
    };

    // ---- A producer: thread loads rows (tid>>3)+{0,32,64,96}, c4 block tid&7
    const int arow = tid >> 3;
    const int ac4  = tid & 7;
    float mrow[4], rrow[4];
    if (AMODE == 2) {
        #pragma unroll
        for (int i = 0; i < 4; i++) {
            int gr = row0 + arow + i * 32;
            mrow[i] = p0[gr];
            rrow[i] = p1[gr];
        }
    }

    auto fetch4 = [&](int i, int c) -> float4 {
        int gr = row0 + arow + i * 32;
        float4 v;
        if (AMODE == 0) {
            v = *(const float4*)(A0 + (size_t)gr * K + c);
        } else {
            v = (c < 128) ? *(const float4*)(A0 + (size_t)gr * 128 + c)
                          : *(const float4*)(A1 + (size_t)gr * 128 + (c - 128));
            if (AMODE == 1) {
                if (c >= 128) {
                    float4 s = *(const float4*)(p0 + c - 128);
                    float4 h = *(const float4*)(p1 + c - 128);
                    v.x = v.x * s.x + h.x; v.y = v.y * s.y + h.y;
                    v.z = v.z * s.z + h.z; v.w = v.w * s.w + h.w;
                }
            } else if (AMODE == 2) {
                float4 g = *(const float4*)(p2 + c);
                float4 bb = *(const float4*)(p3 + c);
                float mn = mrow[i], rs = rrow[i];
                v.x = (v.x - mn) * rs * g.x + bb.x;
                v.y = (v.y - mn) * rs * g.y + bb.y;
                v.z = (v.z - mn) * rs * g.z + bb.z;
                v.w = (v.w - mn) * rs * g.w + bb.w;
            } else {            // AMODE 3: relu(bn1)*bn2 fold on A1
                if (c >= 128) {
                    float4 sa = *(const float4*)(p0 + c - 128);
                    float4 ha = *(const float4*)(p1 + c - 128);
                    float4 sb = *(const float4*)(p2 + c - 128);
                    float4 hb = *(const float4*)(p3 + c - 128);
                    v.x = fmaxf(v.x * sa.x + ha.x, 0.f) * sb.x + hb.x;
                    v.y = fmaxf(v.y * sa.y + ha.y, 0.f) * sb.y + hb.y;
                    v.z = fmaxf(v.z * sa.z + ha.z, 0.f) * sb.z + hb.z;
                    v.w = fmaxf(v.w * sa.w + ha.w, 0.f) * sb.w + hb.w;
                }
            }
        }
        return v;
    };

    float4 pa[2][4];
    auto gather = [&](int kc, int set) {
        int c = kc + ac4 * 4;
        #pragma unroll
        for (int i = 0; i < 4; i++) pa[set][i] = fetch4(i, c);
    };

    loadB();
    gather(0, 0);
    gather(32, 1);

    float acc[2][8][4] = {};
    constexpr int NS = K / 32;

    #pragma unroll
    for (int s = 0; s < NS; s++) {
        const int set = s & 1;
        char* Ab = Asb + set * 8192;
        // STS.64, swizzled 8B groups: addr(row,g) = row*64 + 8*(g ^ (row&7))
        #pragma unroll
        for (int i = 0; i < 4; i++) {
            int row = arow + i * 32;
            uint2 hv = make_uint2(pack2(pa[set][i].x, pa[set][i].y),
                                  pack2(pa[set][i].z, pa[set][i].w));
            *(uint2*)(Ab + row * 64 + 8 * (ac4 ^ (row & 7))) = hv;
        }
        __syncthreads();
        if (s + 2 < NS) gather((s + 2) * 32, set);
        #pragma unroll
        for (int kc = 0; kc < 2; kc++) {
            const int g   = kc * 4 + (lc >> 1);
            const int g2  = g + 2;
            const int off = (lc & 1) * 4;
            uint32_t af[2][4];
            #pragma unroll
            for (int mt2 = 0; mt2 < 2; mt2++) {
                int r = wm * 32 + mt2 * 16 + lr;
                int q = r & 7;                     // == lr
                const char* r1p = Ab + r * 64 + off;
                const char* r2p = Ab + (r + 8) * 64 + off;
                af[mt2][0] = *(const uint32_t*)(r1p + 8 * (g  ^ q));
                af[mt2][1] = *(const uint32_t*)(r2p + 8 * (g  ^ q));
                af[mt2][2] = *(const uint32_t*)(r1p + 8 * (g2 ^ q));
                af[mt2][3] = *(const uint32_t*)(r2p + 8 * (g2 ^ q));
            }
            const int cb = (s * 2 + kc) * 16 + wn * 8;
            #pragma unroll
            for (int u = 0; u < 8; u++) {
                uint2 b = Bs[(cb + u) * 32 + lane];
                mma_f16(acc[0][u], af[0][0], af[0][1], af[0][2], af[0][3], b.x, b.y);
                mma_f16(acc[1][u], af[1][0], af[1][1], af[1][2], af[1][3], b.x, b.y);
            }
        }
    }

    const int ec = lc * 2;
    #pragma unroll
    for (int t = 0; t < 2; t++) {
        int m0 = row0 + wm * 32 + t * 16 + lr;
        #pragma unroll
        for (int u = 0; u < 8; u++) {
            int n = wn * 64 + u * 8 + ec;
            float b0 = bias[n], b1 = bias[n + 1];
            float v0 = acc[t][u][0] + b0;
            float v1 = acc[t][u][1] + b1;
            float v2 = acc[t][u][2] + b0;
            float v3 = acc[t][u][3] + b1;
            if (EPI == EPI_GELU) {
                v0 = 0.5f * v0 * (1.0f + erff(v0 * 0.70710678f));
                v1 = 0.5f * v1 * (1.0f + erff(v1 * 0.70710678f));
                v2 = 0.5f * v2 * (1.0f + erff(v2 * 0.70710678f));
                v3 = 0.5f * v3 * (1.0f + erff(v3 * 0.70710678f));
            } else if (EPI == EPI_RES) {
                float2 r0 = *(const float2*)(res + (size_t)m0 * 128 + n);
                float2 rr = *(const float2*)(res + (size_t)(m0 + 8) * 128 + n);
                v0 += r0.x; v1 += r0.y; v2 += rr.x; v3 += rr.y;
            }
            *(float2*)(Cm + (size_t)m0 * 128 + n)       = make_float2(v0, v1);
            *(float2*)(Cm + (size_t)(m0 + 8) * 128 + n) = make_float2(v2, v3);
        }
    }
}

// ---------------------------------------------------------------------------
// LayerNorm stats only: per-token mean & rstd over the 256-wide concat
// ---------------------------------------------------------------------------
__global__ void ln_stats_k(const float* __restrict__ x1a, const float* __restrict__ x2a,
                           float* __restrict__ mean, float* __restrict__ rstd) {
    int warp = (blockIdx.x * blockDim.x + threadIdx.x) >> 5;
    int lane = threadIdx.x & 31;
    if (warp >= Mm) return;
    float s = 0.f, sq = 0.f;
    #pragma unroll
    for (int kq = 0; kq < 4; kq++) {
        float a = x1a[(size_t)warp * 128 + lane + 32 * kq];
        float b = x2a[(size_t)warp * 128 + lane + 32 * kq];
        s += a + b; sq += a * a + b * b;
    }
    #pragma unroll
    for (int o = 16; o > 0; o >>= 1) {
        s  += __shfl_xor_sync(0xffffffffu, s, o);
        sq += __shfl_xor_sync(0xffffffffu, sq, o);
    }
    if (lane == 0) {
        float mu = s * (1.f / 256.f);
        float var = sq * (1.f / 256.f) - mu * mu;
        mean[warp] = mu;
        rstd[warp] = rsqrtf(var + 1e-5f);
    }
}

// ---------------------------------------------------------------------------
// Window attention on tensor cores (tf32, validated R5/R13). 98 KB smem.
// ---------------------------------------------------------------------------
constexpr int QS_STRIDE = 132;
constexpr int VS_STRIDE = 128;
constexpr int PS_STRIDE = 68;
constexpr int ATTN_SMEM = (2 * 64 * QS_STRIDE + 64 * VS_STRIDE) * 4;   // 98 KB

__launch_bounds__(256)
__global__ void attn_k(const float* __restrict__ q, const float* __restrict__ k,
                       const float* __restrict__ v, float* __restrict__ out) {
    extern __shared__ float sm[];
    float* Qs = sm;
    float* Ks = Qs + 64 * QS_STRIDE;
    float* Vs = Ks + 64 * QS_STRIDE;
    float* Ps = Qs;                       // alias: Q dead after S-mma

    const int widx = blockIdx.x;
    const int b = widx >> 6, wh = (widx >> 3) & 7, ww = widx & 7;
    const int tid  = threadIdx.x;
    const int lane = tid & 31, w = tid >> 5;
    const int wm = w & 3, wn = w >> 2;
    const int lr = lane >> 2, lc = lane & 3;

    auto grow = [&](int i) -> size_t {
        return ((size_t)(b * Nn + (wh * 7 + i / 7) * 56 + ww * 7 + (i % 7))) * 128;
    };

    for (int e = tid; e < 49 * 32; e += 256) {
        int i = e >> 5, c4 = (e & 31) * 4;
        size_t g = grow(i) + c4;
        float4 a  = *(const float4*)(q + g);
        float4 kk = *(const float4*)(k + g);
        float4 vv = *(const float4*)(v + g);
        *(float4*)(Qs + i * QS_STRIDE + c4) =
            make_float4(tf32r(a.x), tf32r(a.y), tf32r(a.z), tf32r(a.w));
        *(float4*)(Ks + i * QS_STRIDE + c4) =
            make_float4(tf32r(kk.x), tf32r(kk.y), tf32r(kk.z), tf32r(kk.w));
        *(float4*)(Vs + i * VS_STRIDE + c4) =
            make_float4(tf32r(vv.x), tf32r(vv.y), tf32r(vv.z), tf32r(vv.w));
    }
    for (int e = tid; e < 15 * VS_STRIDE; e += 256) Vs[49 * VS_STRIDE + e] = 0.f;
    __syncthreads();

    float acc[4][4] = {};
    #pragma unroll
    for (int k8 = 0; k8 < 16; k8++) {
        int r = wm * 16 + lr, c = k8 * 8 + lc;
        float4 a = make_float4(Qs[r * QS_STRIDE + c],     Qs[(r + 8) * QS_STRIDE + c],
                               Qs[r * QS_STRIDE + c + 4], Qs[(r + 8) * QS_STRIDE + c + 4]);
        #pragma unroll
        for (int u = 0; u < 4; u++) {
            int n = wn * 32 + u * 8 + lr;
            float2 bf = make_float2(Ks[n * QS_STRIDE + c], Ks[n * QS_STRIDE + c + 4]);
            mma_tf32(acc[u], a, bf);
        }
    }
    __syncthreads();
    #pragma unroll
    for (int u = 0; u < 4; u++) {
        int r = wm * 16 + lr, n = wn * 32 + u * 8 + lc * 2;
        *(float2*)(Ps + r * PS_STRIDE + n)       = make_float2(acc[u][0], acc[u][1]);
        *(float2*)(Ps + (r + 8) * PS_STRIDE + n) = make_float2(acc[u][2], acc[u][3]);
    }
    __syncthreads();

    if (tid < 49) {
        const float scale = 0.08838834764831845f;
        float* r = Ps + tid * PS_STRIDE;
        float mx = r[0];
        #pragma unroll 7
        for (int j = 1; j < 49; j++) mx = fmaxf(mx, r[j]);
        float s = 0.f;
        #pragma unroll 7
        for (int j = 0; j < 49; j++) { float e = expf((r[j] - mx) * scale); r[j] = e; s += e; }
        float inv = 1.f / s;
        #pragma unroll 7
        for (int j = 0; j < 49; j++) r[j] = tf32r(r[j] * inv);
        #pragma unroll
        for (int j = 49; j < 64; j++) r[j] = 0.f;
    }
    __syncthreads();

    float o[8][4] = {};
    #pragma unroll
    for (int k8 = 0; k8 < 8; k8++) {
        int r = wm * 16 + lr, c = k8 * 8 + lc;
        float4 a = make_float4(Ps[r * PS_STRIDE + c],     Ps[(r + 8) * PS_STRIDE + c],
                               Ps[r * PS_STRIDE + c + 4], Ps[(r + 8) * PS_STRIDE + c + 4]);
        #pragma unroll
        for (int u = 0; u < 8; u++) {
            int n = wn * 64 + u * 8 + lr;
            float2 bf = make_float2(Vs[c * VS_STRIDE + n], Vs[(c + 4) * VS_STRIDE + n]);
            mma_tf32(o[u], a, bf);
        }
    }
    int r0 = wm * 16 + lr;
    #pragma unroll
    for (int u = 0; u < 8; u++) {
        int n = wn * 64 + u * 8 + lc * 2;
        if (r0 < 49)     *(float2*)(out + grow(r0) + n)     = make_float2(o[u][0], o[u][1]);
        if (r0 + 8 < 49) *(float2*)(out + grow(r0 + 8) + n) = make_float2(o[u][2], o[u][3]);
    }
}

// ---------------------------------------------------------------------------
// BatchNorm pieces
// ---------------------------------------------------------------------------
__global__ void bn_stats_k(const float* __restrict__ x, float* __restrict__ part) {
    int c = threadIdx.x & 127;
    int half = threadIdx.x >> 7;
    float s = 0.f, sq = 0.f;
    int rbeg = blockIdx.x * 128 + half;
    int rend = blockIdx.x * 128 + 128;
    for (int r = rbeg; r < rend; r += 2) {
        float vv = x[(size_t)r * 128 + c];
        s += vv; sq += vv * vv;
    }
    __shared__ float sh[512];
    sh[threadIdx.x] = s;
    sh[256 + threadIdx.x] = sq;
    __syncthreads();
    if (half == 0) {
        part[blockIdx.x * 256 + c]       = sh[c] + sh[128 + c];
        part[blockIdx.x * 256 + 128 + c] = sh[256 + c] + sh[256 + 128 + c];
    }
}

__global__ void bn2_stats_k(const float* __restrict__ x,
                            const float* __restrict__ s1, const float* __restrict__ h1,
                            float* __restrict__ part) {
    int c = threadIdx.x & 127;
    int half = threadIdx.x >> 7;
    float sc = s1[c], sh_ = h1[c];
    float s = 0.f, sq = 0.f;
    int rbeg = blockIdx.x * 128 + half;
    int rend = blockIdx.x * 128 + 128;
    for (int r = rbeg; r < rend; r += 2) {
        float vv = fmaxf(x[(size_t)r * 128 + c] * sc + sh_, 0.f);
        s += vv; sq += vv * vv;
    }
    __shared__ float shm[512];
    shm[threadIdx.x] = s;
    shm[256 + threadIdx.x] = sq;
    __syncthreads();
    if (half == 0) {
        part[blockIdx.x * 256 + c]       = shm[c] + shm[128 + c];
        part[blockIdx.x * 256 + 128 + c] = shm[256 + c] + shm[256 + 128 + c];
    }
}

__global__ void bn_reduce_k(const float* __restrict__ part, const float* __restrict__ g,
                            const float* __restrict__ beta, float* __restrict__ scale,
                            float* __restrict__ shift) {
    int c = threadIdx.x;
    float s = 0.f, sq = 0.f;
    for (int i = 0; i < 784; i++) {
        s  += part[i * 256 + c];
        sq += part[i * 256 + 128 + c];
    }
    float mean = s / (float)Mm;
    float var  = sq / (float)Mm - mean * mean;
    float sc_  = g[c] * rsqrtf(var + 1e-5f);
    scale[c] = sc_;
    shift[c] = beta[c] - mean * sc_;
}

// ---------------------------------------------------------------------------
// Host launch
// ---------------------------------------------------------------------------
static float* symaddr(const void* devsym) {
    void* p = nullptr;
    cudaGetSymbolAddress(&p, devsym);
    return (float*)p;
}

extern "C" void kernel_launch(void* const* d_in, const int* in_sizes, int n_in,
                              void* d_out, int out_size) {
    const float* x     = (const float*)d_in[0];
    const float* fc1_w = (const float*)d_in[1];
    const float* fc1_b = (const float*)d_in[2];
    const float* fc2_w = (const float*)d_in[3];
    const float* fc2_b = (const float*)d_in[4];
    const float* fc3_w = (const float*)d_in[5];
    const float* fc3_b = (const float*)d_in[6];
    const float* fc4_w = (const float*)d_in[7];
    const float* fc4_b = (const float*)d_in[8];
    const float* fc5_w = (const float*)d_in[9];
    const float* fc5_b = (const float*)d_in[10];
    const float* fc6_w = (const float*)d_in[11];
    const float* fc6_b = (const float*)d_in[12];
    const float* ln_w  = (const float*)d_in[13];
    const float* ln_b  = (const float*)d_in[14];
    const float* q_w   = (const float*)d_in[15];
    const float* q_b   = (const float*)d_in[16];
    const float* k_w   = (const float*)d_in[17];
    const float* k_b   = (const float*)d_in[18];
    const float* v_w   = (const float*)d_in[19];
    const float* v_b   = (const float*)d_in[20];
    const float* bn1_g = (const float*)d_in[21];
    const float* bn1_b = (const float*)d_in[22];
    const float* bn2_g = (const float*)d_in[23];
    const float* bn2_b = (const float*)d_in[24];

    float* t0   = symaddr(g_t0);
    float* t1   = symaddr(g_t1);
    float* x1a  = symaddr(g_x1a);
    float* x2a  = symaddr(g_x2a);
    float* qb   = symaddr(g_q);
    float* kb   = symaddr(g_k);
    float* vb   = symaddr(g_v);
    float* att  = symaddr(g_att);
    float* stat = symaddr(g_stats);
    float* mean = stat;
    float* rstd = stat + Mm;
    float* part = symaddr(g_part);
    float* s1   = symaddr(g_s1);
    float* h1   = symaddr(g_h1);
    float* s2   = symaddr(g_s2);
    float* h2   = symaddr(g_h2);

    const int gridR = Bb * 56;
    const int gridG = Mm / 128;          // 784

    auto setsm = [](const void* f) {
        cudaFuncSetAttribute(f, cudaFuncAttributeMaxDynamicSharedMemorySize, SM_ALL);
    };
    setsm((const void*)gemm_k<128, EPI_GELU, 0, false, false>);
    setsm((const void*)gemm_k<128, EPI_RES,  0, false, false>);
    setsm((const void*)gemm_k<128, EPI_BIAS, 0, true,  true >);
    setsm((const void*)gemm_k<256, EPI_RES,  2, false, false>);
    setsm((const void*)gemm_k<256, EPI_BIAS, 3, false, false>);
    cudaFuncSetAttribute(attn_k, cudaFuncAttributeMaxDynamicSharedMemorySize, ATTN_SMEM);

    #define GEMM_ARGS(A0,A1,B,bias,res,q0,q1,q2,q3,C) \
        A0, A1, B, nullptr, nullptr, bias, nullptr, nullptr, res, q0, q1, q2, q3, C, nullptr, nullptr

    // Branch 1
    roll_k<0><<<gridR, 256>>>(x, t0);
    gemm_k<128, EPI_GELU, 0, false, false><<<gridG, 256, SM_ALL>>>(
        GEMM_ARGS(t0, nullptr, fc1_w, fc1_b, nullptr, nullptr, nullptr, nullptr, nullptr, t1));
    roll_k<1><<<gridR, 256>>>(t1, t0);
    gemm_k<128, EPI_RES, 0, false, false><<<gridG, 256, SM_ALL>>>(
        GEMM_ARGS(t0, nullptr, fc2_w, fc2_b, x, nullptr, nullptr, nullptr, nullptr, x1a));

    // Branch 2
    roll_k<2><<<gridR, 256>>>(x, t0);
    gemm_k<128, EPI_GELU, 0, false, false><<<gridG, 256, SM_ALL>>>(
        GEMM_ARGS(t0, nullptr, fc3_w, fc3_b, nullptr, nullptr, nullptr, nullptr, nullptr, t1));
    roll_k<0><<<gridR, 256>>>(t1, t0);
    gemm_k<128, EPI_RES, 0, false, false><<<gridG, 256, SM_ALL>>>(
        GEMM_ARGS(t0, nullptr, fc4_w, fc4_b, x, nullptr, nullptr, nullptr, nullptr, x2a));

    // LN stats + fc5 (LN folded into A-gather) + residual -> t0
    ln_stats_k<<<Mm / 8, 256>>>(x1a, x2a, mean, rstd);
    gemm_k<256, EPI_RES, 2, false, false><<<gridG, 256, SM_ALL>>>(
        x1a, x2a, fc5_w, nullptr, nullptr, fc5_b, nullptr, nullptr, x,
        mean, rstd, ln_w, ln_b, t0, nullptr, nullptr);

    // q/k/v in one launch (grid.y selects weight/bias/output)
    gemm_k<128, EPI_BIAS, 0, true, true><<<dim3(gridG, 3), 256, SM_ALL>>>(
        x, nullptr, q_w, k_w, v_w, q_b, k_b, v_b, nullptr,
        nullptr, nullptr, nullptr, nullptr, qb, kb, vb);

    // Window attention (tensor cores, 2 CTAs/SM)
    attn_k<<<2048, 256, ATTN_SMEM>>>(qb, kb, vb, att);

    // BN1 stats -> reduce -> BN2 stats (read-only, relu(bn1) on the fly) -> reduce
    bn_stats_k<<<784, 256>>>(att, part);
    bn_reduce_k<<<1, 128>>>(part, bn1_g, bn1_b, s1, h1);
    bn2_stats_k<<<784, 256>>>(att, s1, h1, part);
    bn_reduce_k<<<1, 128>>>(part, bn2_g, bn2_b, s2, h2);

    // Final: out = [x1 | relu(bn1(att))*bn2] @ fc6 + b  (full fold in A-gather)
    gemm_k<256, EPI_BIAS, 3, false, false><<<gridG, 256, SM_ALL>>>(
        t0, att, fc6_w, nullptr, nullptr, fc6_b, nullptr, nullptr, nullptr,
        s1, h1, s2, h2, (float*)d_out, nullptr, nullptr);
}

// round 15
// speedup vs baseline: 1.4123x; 1.0585x over previous
#include <cuda_runtime.h>
#include <cuda_fp16.h>
#include <math.h>
#include <stdint.h>

constexpr int Bb = 32;
constexpr int Hh = 56;
constexpr int Ww = 56;
constexpr int Cc = 128;
constexpr int Nn = Hh * Ww;              // 3136
constexpr int Mm = Bb * Nn;              // 100352
constexpr size_t MC = (size_t)Mm * Cc;

__device__ float g_t0[MC];
__device__ float g_t1[MC];
__device__ float g_x1a[MC];
__device__ float g_x2a[MC];
__device__ float g_q[MC];
__device__ float g_k[MC];
__device__ float g_v[MC];
__device__ float g_att[MC];
__device__ float g_stats[2 * Mm];
__device__ float g_part[784 * 256];
__device__ float g_s1[Cc];
__device__ float g_h1[Cc];
__device__ float g_s2[Cc];
__device__ float g_h2[Cc];

__device__ __forceinline__ void mma_tf32(float* c, const float4& a, const float2& b) {
    asm volatile(
        "mma.sync.aligned.m16n8k8.row.col.f32.tf32.tf32.f32 "
        "{%0,%1,%2,%3}, {%4,%5,%6,%7}, {%8,%9}, {%0,%1,%2,%3};"
        : "+f"(c[0]), "+f"(c[1]), "+f"(c[2]), "+f"(c[3])
        : "r"(__float_as_uint(a.x)), "r"(__float_as_uint(a.y)),
          "r"(__float_as_uint(a.z)), "r"(__float_as_uint(a.w)),
          "r"(__float_as_uint(b.x)), "r"(__float_as_uint(b.y)));
}

__device__ __forceinline__ void mma_f16(float* c, uint32_t a0, uint32_t a1,
                                        uint32_t a2, uint32_t a3,
                                        uint32_t b0, uint32_t b1) {
    asm volatile(
        "mma.sync.aligned.m16n8k16.row.col.f32.f16.f16.f32 "
        "{%0,%1,%2,%3}, {%4,%5,%6,%7}, {%8,%9}, {%0,%1,%2,%3};"
        : "+f"(c[0]), "+f"(c[1]), "+f"(c[2]), "+f"(c[3])
        : "r"(a0), "r"(a1), "r"(a2), "r"(a3), "r"(b0), "r"(b1));
}

__device__ __forceinline__ uint32_t pack2(float x, float y) {
    __half2 h = __floats2half2_rn(x, y);
    return *reinterpret_cast<uint32_t*>(&h);
}

// ---------------------------------------------------------------------------
// Per-channel roll. MODE 0: H,+c  1: W,+c  2: W,-c
// ---------------------------------------------------------------------------
template <int MODE>
__launch_bounds__(256)
__global__ void roll_k(const float* __restrict__ in, float* __restrict__ out) {
    __shared__ float tile[56 * 128];
    const int tid = threadIdx.x;
    const int b = blockIdx.x / 56;
    const int f = blockIdx.x % 56;
    const size_t base   = (MODE == 0) ? ((size_t)b * Nn + f) * 128
                                      : ((size_t)(b * 56 + f) * 56) * 128;
    const int    stride = (MODE == 0) ? 56 * 128 : 128;

    #pragma unroll
    for (int e = tid; e < 56 * 32; e += 256) {
        int rowi = e >> 5, c4 = e & 31;
        ((float4*)tile)[rowi * 32 + c4] =
            *(const float4*)(in + base + (size_t)rowi * stride + c4 * 4);
    }
    __syncthreads();

    #pragma unroll
    for (int e = tid; e < 56 * 128; e += 256) {
        int pos = e >> 7, c = e & 127;
        int cm = c % 56;
        int src = (MODE == 2) ? pos + cm : pos - cm;
        if (src < 0) src += 56;
        if (src >= 56) src -= 56;
        out[base + (size_t)pos * stride + c] = tile[src * 128 + c];
    }
}

// ---------------------------------------------------------------------------
// FP16 GEMM (m16n8k16, fp32 accum), R14-validated structure.
// MULTI: 0 single; 1 QKV (y selects B/bias/C, shared A); 2 DUAL (y selects
// A/B/bias/C pair, shared res). AMODE: 0 plain; 1 BN-affine on A1;
// 2 LN fold; 3 relu(bn1)*bn2 fold.
// ---------------------------------------------------------------------------
enum { EPI_GELU = 0, EPI_BIAS = 1, EPI_RES = 2 };
constexpr int SM_ALL = 64 * 1024 + 16 * 1024;

template <int K, int EPI, int AMODE, bool BT, int MULTI>
__launch_bounds__(256, 2)
__global__ void gemm_k(const float* __restrict__ A0, const float* __restrict__ A1,
                       const float* __restrict__ B0, const float* __restrict__ B1,
                       const float* __restrict__ B2,
                       const float* __restrict__ bias0, const float* __restrict__ bias1,
                       const float* __restrict__ bias2,
                       const float* __restrict__ res,
                       const float* __restrict__ p0, const float* __restrict__ p1,
                       const float* __restrict__ p2, const float* __restrict__ p3,
                       float* __restrict__ C0, float* __restrict__ C1,
                       float* __restrict__ C2) {
    extern __shared__ char smemc[];
    uint2* Bs  = (uint2*)smemc;
    char*  Asb = smemc + 65536;

    const float* Am = A0;
    const float* Bm = B0;
    const float* bias = bias0;
    float* Cm = C0;
    if (MULTI == 1) {
        int y = blockIdx.y;
        if (y == 1) { Bm = B1; bias = bias1; Cm = C1; }
        else if (y == 2) { Bm = B2; bias = bias2; Cm = C2; }
    } else if (MULTI == 2) {
        if (blockIdx.y == 1) { Am = A1; Bm = B1; bias = bias1; Cm = C1; }
    }

    const int tid  = threadIdx.x;
    const int lane = tid & 31;
    const int wid  = tid >> 5;
    const int wm   = wid & 3;
    const int wn   = wid >> 2;
    const int row0 = blockIdx.x * 128;
    const int lr   = lane >> 2;
    const int lc   = lane & 3;

    auto loadB = [&]() {
        for (int frag = wid; frag < (K / 16) * 16; frag += 8) {
            int kc = frag >> 4, nt = frag & 15;
            int kk = kc * 16 + lc * 2, n = nt * 8 + lr;
            float v0, v1, v2, v3;
            if (BT) {
                const float* p = Bm + (size_t)n * K + kk;
                v0 = p[0]; v1 = p[1]; v2 = p[8]; v3 = p[9];
            } else {
                v0 = Bm[(size_t)kk * 128 + n];
                v1 = Bm[(size_t)(kk + 1) * 128 + n];
                v2 = Bm[(size_t)(kk + 8) * 128 + n];
                v3 = Bm[(size_t)(kk + 9) * 128 + n];
            }
            Bs[frag * 32 + lane] = make_uint2(pack2(v0, v1), pack2(v2, v3));
        }
    };

    const int arow = tid >> 3;
    const int ac4  = tid & 7;
    float mrow[4], rrow[4];
    if (AMODE == 2) {
        #pragma unroll
        for (int i = 0; i < 4; i++) {
            int gr = row0 + arow + i * 32;
            mrow[i] = p0[gr];
            rrow[i] = p1[gr];
        }
    }

    auto fetch4 = [&](int i, int c) -> float4 {
        int gr = row0 + arow + i * 32;
        float4 v;
        if (AMODE == 0) {
            v = *(const float4*)(Am + (size_t)gr * K + c);
        } else {
            v = (c < 128) ? *(const float4*)(A0 + (size_t)gr * 128 + c)
                          : *(const float4*)(A1 + (size_t)gr * 128 + (c - 128));
            if (AMODE == 1) {
                if (c >= 128) {
                    float4 s = *(const float4*)(p0 + c - 128);
                    float4 h = *(const float4*)(p1 + c - 128);
                    v.x = v.x * s.x + h.x; v.y = v.y * s.y + h.y;
                    v.z = v.z * s.z + h.z; v.w = v.w * s.w + h.w;
                }
            } else if (AMODE == 2) {
                float4 g = *(const float4*)(p2 + c);
                float4 bb = *(const float4*)(p3 + c);
                float mn = mrow[i], rs = rrow[i];
                v.x = (v.x - mn) * rs * g.x + bb.x;
                v.y = (v.y - mn) * rs * g.y + bb.y;
                v.z = (v.z - mn) * rs * g.z + bb.z;
                v.w = (v.w - mn) * rs * g.w + bb.w;
            } else {
                if (c >= 128) {
                    float4 sa = *(const float4*)(p0 + c - 128);
                    float4 ha = *(const float4*)(p1 + c - 128);
                    float4 sb = *(const float4*)(p2 + c - 128);
                    float4 hb = *(const float4*)(p3 + c - 128);
                    v.x = fmaxf(v.x * sa.x + ha.x, 0.f) * sb.x + hb.x;
                    v.y = fmaxf(v.y * sa.y + ha.y, 0.f) * sb.y + hb.y;
                    v.z = fmaxf(v.z * sa.z + ha.z, 0.f) * sb.z + hb.z;
                    v.w = fmaxf(v.w * sa.w + ha.w, 0.f) * sb.w + hb.w;
                }
            }
        }
        return v;
    };

    float4 pa[2][4];
    auto gather = [&](int kc, int set) {
        int c = kc + ac4 * 4;
        #pragma unroll
        for (int i = 0; i < 4; i++) pa[set][i] = fetch4(i, c);
    };

    loadB();
    gather(0, 0);
    gather(32, 1);

    float acc[2][8][4] = {};
    constexpr int NS = K / 32;

    #pragma unroll
    for (int s = 0; s < NS; s++) {
        const int set = s & 1;
        char* Ab = Asb + set * 8192;
        #pragma unroll
        for (int i = 0; i < 4; i++) {
            int row = arow + i * 32;
            uint2 hv = make_uint2(pack2(pa[set][i].x, pa[set][i].y),
                                  pack2(pa[set][i].z, pa[set][i].w));
            *(uint2*)(Ab + row * 64 + 8 * (ac4 ^ (row & 7))) = hv;
        }
        __syncthreads();
        if (s + 2 < NS) gather((s + 2) * 32, set);
        #pragma unroll
        for (int kc = 0; kc < 2; kc++) {
            const int g   = kc * 4 + (lc >> 1);
            const int g2  = g + 2;
            const int off = (lc & 1) * 4;
            uint32_t af[2][4];
            #pragma unroll
            for (int mt2 = 0; mt2 < 2; mt2++) {
                int r = wm * 32 + mt2 * 16 + lr;
                int q = r & 7;
                const char* r1p = Ab + r * 64 + off;
                const char* r2p = Ab + (r + 8) * 64 + off;
                af[mt2][0] = *(const uint32_t*)(r1p + 8 * (g  ^ q));
                af[mt2][1] = *(const uint32_t*)(r2p + 8 * (g  ^ q));
                af[mt2][2] = *(const uint32_t*)(r1p + 8 * (g2 ^ q));
                af[mt2][3] = *(const uint32_t*)(r2p + 8 * (g2 ^ q));
            }
            const int cb = (s * 2 + kc) * 16 + wn * 8;
            #pragma unroll
            for (int u = 0; u < 8; u++) {
                uint2 b = Bs[(cb + u) * 32 + lane];
                mma_f16(acc[0][u], af[0][0], af[0][1], af[0][2], af[0][3], b.x, b.y);
                mma_f16(acc[1][u], af[1][0], af[1][1], af[1][2], af[1][3], b.x, b.y);
            }
        }
    }

    const int ec = lc * 2;
    #pragma unroll
    for (int t = 0; t < 2; t++) {
        int m0 = row0 + wm * 32 + t * 16 + lr;
        #pragma unroll
        for (int u = 0; u < 8; u++) {
            int n = wn * 64 + u * 8 + ec;
            float b0 = bias[n], b1 = bias[n + 1];
            float v0 = acc[t][u][0] + b0;
            float v1 = acc[t][u][1] + b1;
            float v2 = acc[t][u][2] + b0;
            float v3 = acc[t][u][3] + b1;
            if (EPI == EPI_GELU) {
                v0 = 0.5f * v0 * (1.0f + erff(v0 * 0.70710678f));
                v1 = 0.5f * v1 * (1.0f + erff(v1 * 0.70710678f));
                v2 = 0.5f * v2 * (1.0f + erff(v2 * 0.70710678f));
                v3 = 0.5f * v3 * (1.0f + erff(v3 * 0.70710678f));
            } else if (EPI == EPI_RES) {
                float2 r0 = *(const float2*)(res + (size_t)m0 * 128 + n);
                float2 rr = *(const float2*)(res + (size_t)(m0 + 8) * 128 + n);
                v0 += r0.x; v1 += r0.y; v2 += rr.x; v3 += rr.y;
            }
            *(float2*)(Cm + (size_t)m0 * 128 + n)       = make_float2(v0, v1);
            *(float2*)(Cm + (size_t)(m0 + 8) * 128 + n) = make_float2(v2, v3);
        }
    }
}

// ---------------------------------------------------------------------------
// LayerNorm stats only
// ---------------------------------------------------------------------------
__global__ void ln_stats_k(const float* __restrict__ x1a, const float* __restrict__ x2a,
                           float* __restrict__ mean, float* __restrict__ rstd) {
    int warp = (blockIdx.x * blockDim.x + threadIdx.x) >> 5;
    int lane = threadIdx.x & 31;
    if (warp >= Mm) return;
    float s = 0.f, sq = 0.f;
    #pragma unroll
    for (int kq = 0; kq < 4; kq++) {
        float a = x1a[(size_t)warp * 128 + lane + 32 * kq];
        float b = x2a[(size_t)warp * 128 + lane + 32 * kq];
        s += a + b; sq += a * a + b * b;
    }
    #pragma unroll
    for (int o = 16; o > 0; o >>= 1) {
        s  += __shfl_xor_sync(0xffffffffu, s, o);
        sq += __shfl_xor_sync(0xffffffffu, sq, o);
    }
    if (lane == 0) {
        float mu = s * (1.f / 256.f);
        float var = sq * (1.f / 256.f) - mu * mu;
        mean[warp] = mu;
        rstd[warp] = rsqrtf(var + 1e-5f);
    }
}

// ---------------------------------------------------------------------------
// Window attention: fp16 smem, fp16 QK-mma (m16n8k16), tf32 PV-mma from fp16.
// Qs/Ks stride 136 halfs (bank 4r+lc distinct). P (stride 72) aliases Q.
// V token-major stride 136 (LDS.16 pairs merge to same word). 51 KB smem.
// ---------------------------------------------------------------------------
constexpr int QH = 136;
constexpr int PH = 72;
constexpr int VH = 136;
constexpr int ATTN_SMEM = (2 * 64 * QH + 64 * VH) * 2;   // 52224 B

__launch_bounds__(256)
__global__ void attn_k(const float* __restrict__ q, const float* __restrict__ k,
                       const float* __restrict__ v, float* __restrict__ out) {
    extern __shared__ __half smh[];
    __half* Qs = smh;
    __half* Ks = Qs + 64 * QH;
    __half* Vs = Ks + 64 * QH;
    __half* Ps = Qs;                     // alias: Q dead after S-mma

    const int widx = blockIdx.x;
    const int b = widx >> 6, wh = (widx >> 3) & 7, ww = widx & 7;
    const int tid  = threadIdx.x;
    const int lane = tid & 31, w = tid >> 5;
    const int wm = w & 3, wn = w >> 2;
    const int lr = lane >> 2, lc = lane & 3;

    auto grow = [&](int i) -> size_t {
        return ((size_t)(b * Nn + (wh * 7 + i / 7) * 56 + ww * 7 + (i % 7))) * 128;
    };

    for (int e = tid; e < 49 * 32; e += 256) {
        int i = e >> 5, c4 = (e & 31) * 4;
        size_t g = grow(i) + c4;
        float4 a  = *(const float4*)(q + g);
        float4 kk = *(const float4*)(k + g);
        float4 vv = *(const float4*)(v + g);
        *(uint2*)(Qs + i * QH + c4) = make_uint2(pack2(a.x, a.y), pack2(a.z, a.w));
        *(uint2*)(Ks + i * QH + c4) = make_uint2(pack2(kk.x, kk.y), pack2(kk.z, kk.w));
        *(uint2*)(Vs + i * VH + c4) = make_uint2(pack2(vv.x, vv.y), pack2(vv.z, vv.w));
    }
    // zero V pad rows 49..63
    for (int e = tid; e < 15 * VH / 2; e += 256)
        ((uint32_t*)(Vs + 49 * VH))[e] = 0u;
    __syncthreads();

    // S = Q K^T  (fp16 m16n8k16, warp tile m16 x n32)
    float acc[4][4] = {};
    #pragma unroll
    for (int ks = 0; ks < 8; ks++) {
        int r = wm * 16 + lr, c = ks * 16 + lc * 2;
        uint32_t a0 = *(const uint32_t*)(Qs + r * QH + c);
        uint32_t a1 = *(const uint32_t*)(Qs + (r + 8) * QH + c);
        uint32_t a2 = *(const uint32_t*)(Qs + r * QH + c + 8);
        uint32_t a3 = *(const uint32_t*)(Qs + (r + 8) * QH + c + 8);
        #pragma unroll
        for (int u = 0; u < 4; u++) {
            int n = wn * 32 + u * 8 + lr;
            uint32_t b0 = *(const uint32_t*)(Ks + n * QH + c);
            uint32_t b1 = *(const uint32_t*)(Ks + n * QH + c + 8);
            mma_f16(acc[u], a0, a1, a2, a3, b0, b1);
        }
    }
    __syncthreads();                      // Qs reads done before Ps writes
    #pragma unroll
    for (int u = 0; u < 4; u++) {
        int r = wm * 16 + lr, n = wn * 32 + u * 8 + lc * 2;
        *(uint32_t*)(Ps + r * PH + n)       = pack2(acc[u][0], acc[u][1]);
        *(uint32_t*)(Ps + (r + 8) * PH + n) = pack2(acc[u][2], acc[u][3]);
    }
    __syncthreads();

    if (tid < 49) {
        const float scale = 0.08838834764831845f;
        __half* r = Ps + tid * PH;
        float mx = __half2float(r[0]);
        #pragma unroll 7
        for (int j = 1; j < 49; j++) mx = fmaxf(mx, __half2float(r[j]));
        float s = 0.f;
        #pragma unroll 7
        for (int j = 0; j < 49; j++) {
            float e = expf((__half2float(r[j]) - mx) * scale);
            r[j] = __float2half(e);
            s += e;
        }
        float inv = 1.f / s;
        #pragma unroll 7
        for (int j = 0; j < 49; j++)
            r[j] = __float2half(__half2float(r[j]) * inv);
        #pragma unroll
        for (int j = 49; j < 64; j++) r[j] = __float2half(0.f);
    }
    __syncthreads();

    // O = P V  (tf32 mma; operands exact fp16 values)
    float o[8][4] = {};
    #pragma unroll
    for (int k8 = 0; k8 < 8; k8++) {
        int r = wm * 16 + lr, c = k8 * 8 + lc;
        float4 a = make_float4(__half2float(Ps[r * PH + c]),
                               __half2float(Ps[(r + 8) * PH + c]),
                               __half2float(Ps[r * PH + c + 4]),
                               __half2float(Ps[(r + 8) * PH + c + 4]));
        #pragma unroll
        for (int u = 0; u < 8; u++) {
            int n = wn * 64 + u * 8 + lr;
            float2 bf = make_float2(__half2float(Vs[c * VH + n]),
                                    __half2float(Vs[(c + 4) * VH + n]));
            mma_tf32(o[u], a, bf);
        }
    }
    int r0 = wm * 16 + lr;
    #pragma unroll
    for (int u = 0; u < 8; u++) {
        int n = wn * 64 + u * 8 + lc * 2;
        if (r0 < 49)     *(float2*)(out + grow(r0) + n)     = make_float2(o[u][0], o[u][1]);
        if (r0 + 8 < 49) *(float2*)(out + grow(r0 + 8) + n) = make_float2(o[u][2], o[u][3]);
    }
}

// ---------------------------------------------------------------------------
// BatchNorm pieces
// ---------------------------------------------------------------------------
__global__ void bn_stats_k(const float* __restrict__ x, float* __restrict__ part) {
    int c = threadIdx.x & 127;
    int half = threadIdx.x >> 7;
    float s = 0.f, sq = 0.f;
    int rbeg = blockIdx.x * 128 + half;
    int rend = blockIdx.x * 128 + 128;
    for (int r = rbeg; r < rend; r += 2) {
        float vv = x[(size_t)r * 128 + c];
        s += vv; sq += vv * vv;
    }
    __shared__ float sh[512];
    sh[threadIdx.x] = s;
    sh[256 + threadIdx.x] = sq;
    __syncthreads();
    if (half == 0) {
        part[blockIdx.x * 256 + c]       = sh[c] + sh[128 + c];
        part[blockIdx.x * 256 + 128 + c] = sh[256 + c] + sh[256 + 128 + c];
    }
}

__global__ void bn2_stats_k(const float* __restrict__ x,
                            const float* __restrict__ s1, const float* __restrict__ h1,
                            float* __restrict__ part) {
    int c = threadIdx.x & 127;
    int half = threadIdx.x >> 7;
    float sc = s1[c], sh_ = h1[c];
    float s = 0.f, sq = 0.f;
    int rbeg = blockIdx.x * 128 + half;
    int rend = blockIdx.x * 128 + 128;
    for (int r = rbeg; r < rend; r += 2) {
        float vv = fmaxf(x[(size_t)r * 128 + c] * sc + sh_, 0.f);
        s += vv; sq += vv * vv;
    }
    __shared__ float shm[512];
    shm[threadIdx.x] = s;
    shm[256 + threadIdx.x] = sq;
    __syncthreads();
    if (half == 0) {
        part[blockIdx.x * 256 + c]       = shm[c] + shm[128 + c];
        part[blockIdx.x * 256 + 128 + c] = shm[256 + c] + shm[256 + 128 + c];
    }
}

__global__ void bn_reduce_k(const float* __restrict__ part, const float* __restrict__ g,
                            const float* __restrict__ beta, float* __restrict__ scale,
                            float* __restrict__ shift) {
    int c = threadIdx.x;
    float s = 0.f, sq = 0.f;
    for (int i = 0; i < 784; i++) {
        s  += part[i * 256 + c];
        sq += part[i * 256 + 128 + c];
    }
    float mean = s / (float)Mm;
    float var  = sq / (float)Mm - mean * mean;
    float sc_  = g[c] * rsqrtf(var + 1e-5f);
    scale[c] = sc_;
    shift[c] = beta[c] - mean * sc_;
}

// ---------------------------------------------------------------------------
// Host launch
// ---------------------------------------------------------------------------
static float* symaddr(const void* devsym) {
    void* p = nullptr;
    cudaGetSymbolAddress(&p, devsym);
    return (float*)p;
}

extern "C" void kernel_launch(void* const* d_in, const int* in_sizes, int n_in,
                              void* d_out, int out_size) {
    const float* x     = (const float*)d_in[0];
    const float* fc1_w = (const float*)d_in[1];
    const float* fc1_b = (const float*)d_in[2];
    const float* fc2_w = (const float*)d_in[3];
    const float* fc2_b = (const float*)d_in[4];
    const float* fc3_w = (const float*)d_in[5];
    const float* fc3_b = (const float*)d_in[6];
    const float* fc4_w = (const float*)d_in[7];
    const float* fc4_b = (const float*)d_in[8];
    const float* fc5_w = (const float*)d_in[9];
    const float* fc5_b = (const float*)d_in[10];
    const float* fc6_w = (const float*)d_in[11];
    const float* fc6_b = (const float*)d_in[12];
    const float* ln_w  = (const float*)d_in[13];
    const float* ln_b  = (const float*)d_in[14];
    const float* q_w   = (const float*)d_in[15];
    const float* q_b   = (const float*)d_in[16];
    const float* k_w   = (const float*)d_in[17];
    const float* k_b   = (const float*)d_in[18];
    const float* v_w   = (const float*)d_in[19];
    const float* v_b   = (const float*)d_in[20];
    const float* bn1_g = (const float*)d_in[21];
    const float* bn1_b = (const float*)d_in[22];
    const float* bn2_g = (const float*)d_in[23];
    const float* bn2_b = (const float*)d_in[24];

    float* t0   = symaddr(g_t0);
    float* t1   = symaddr(g_t1);
    float* x1a  = symaddr(g_x1a);
    float* x2a  = symaddr(g_x2a);
    float* qb   = symaddr(g_q);
    float* kb   = symaddr(g_k);
    float* vb   = symaddr(g_v);
    float* att  = symaddr(g_att);
    float* stat = symaddr(g_stats);
    float* mean = stat;
    float* rstd = stat + Mm;
    float* part = symaddr(g_part);
    float* s1   = symaddr(g_s1);
    float* h1   = symaddr(g_h1);
    float* s2   = symaddr(g_s2);
    float* h2   = symaddr(g_h2);

    const int gridR = Bb * 56;
    const int gridG = Mm / 128;          // 784

    auto setsm = [](const void* f) {
        cudaFuncSetAttribute(f, cudaFuncAttributeMaxDynamicSharedMemorySize, SM_ALL);
    };
    setsm((const void*)gemm_k<128, EPI_GELU, 0, false, 2>);
    setsm((const void*)gemm_k<128, EPI_RES,  0, false, 2>);
    setsm((const void*)gemm_k<128, EPI_BIAS, 0, true,  1>);
    setsm((const void*)gemm_k<256, EPI_RES,  2, false, 0>);
    setsm((const void*)gemm_k<256, EPI_BIAS, 3, false, 0>);
    cudaFuncSetAttribute(attn_k, cudaFuncAttributeMaxDynamicSharedMemorySize, ATTN_SMEM);

    // Rolls of x for both branches (t0 = H,+c ; qb = W,-c)
    roll_k<0><<<gridR, 256>>>(x, t0);
    roll_k<2><<<gridR, 256>>>(x, qb);

    // fc1 || fc3 (DUAL): (t0 x fc1_w -> t1), (qb x fc3_w -> kb), GELU
    gemm_k<128, EPI_GELU, 0, false, 2><<<dim3(gridG, 2), 256, SM_ALL>>>(
        t0, qb, fc1_w, fc3_w, nullptr, fc1_b, fc3_b, nullptr, nullptr,
        nullptr, nullptr, nullptr, nullptr, t1, kb, nullptr);

    // mid rolls
    roll_k<1><<<gridR, 256>>>(t1, t0);
    roll_k<0><<<gridR, 256>>>(kb, qb);

    // fc2 || fc4 (DUAL) + residual x: -> x1a, x2a
    gemm_k<128, EPI_RES, 0, false, 2><<<dim3(gridG, 2), 256, SM_ALL>>>(
        t0, qb, fc2_w, fc4_w, nullptr, fc2_b, fc4_b, nullptr, x,
        nullptr, nullptr, nullptr, nullptr, x1a, x2a, nullptr);

    // LN stats + fc5 (LN folded) + residual -> t0
    ln_stats_k<<<Mm / 8, 256>>>(x1a, x2a, mean, rstd);
    gemm_k<256, EPI_RES, 2, false, 0><<<gridG, 256, SM_ALL>>>(
        x1a, x2a, fc5_w, nullptr, nullptr, fc5_b, nullptr, nullptr, x,
        mean, rstd, ln_w, ln_b, t0, nullptr, nullptr);

    // q/k/v in one launch
    gemm_k<128, EPI_BIAS, 0, true, 1><<<dim3(gridG, 3), 256, SM_ALL>>>(
        x, nullptr, q_w, k_w, v_w, q_b, k_b, v_b, nullptr,
        nullptr, nullptr, nullptr, nullptr, qb, kb, vb);

    // Window attention (fp16, 3 CTAs/SM)
    attn_k<<<2048, 256, ATTN_SMEM>>>(qb, kb, vb, att);

    // BN chain (no write-back; fc6 applies full composite)
    bn_stats_k<<<784, 256>>>(att, part);
    bn_reduce_k<<<1, 128>>>(part, bn1_g, bn1_b, s1, h1);
    bn2_stats_k<<<784, 256>>>(att, s1, h1, part);
    bn_reduce_k<<<1, 128>>>(part, bn2_g, bn2_b, s2, h2);

    // Final: out = [x1 | relu(bn1(att))*bn2] @ fc6 + b
    gemm_k<256, EPI_BIAS, 3, false, 0><<<gridG, 256, SM_ALL>>>(
        t0, att, fc6_w, nullptr, nullptr, fc6_b, nullptr, nullptr, nullptr,
        s1, h1, s2, h2, (float*)d_out, nullptr, nullptr);
}

// round 16
// speedup vs baseline: 1.5920x; 1.1273x over previous
#include <cuda_runtime.h>
#include <cuda_fp16.h>
#include <math.h>
#include <stdint.h>

constexpr int Bb = 32;
constexpr int Hh = 56;
constexpr int Ww = 56;
constexpr int Cc = 128;
constexpr int Nn = Hh * Ww;              // 3136
constexpr int Mm = Bb * Nn;              // 100352
constexpr size_t MC = (size_t)Mm * Cc;

__device__ float g_t0[MC];
__device__ float g_t1[MC];
__device__ float g_x1a[MC];
__device__ float g_x2a[MC];
__device__ float g_q[MC];
__device__ float g_k[MC];
__device__ float g_v[MC];
__device__ float g_att[MC];
__device__ float g_stats[2 * Mm];
__device__ float g_part[784 * 256];
__device__ float g_s1[Cc];
__device__ float g_h1[Cc];
__device__ float g_s2[Cc];
__device__ float g_h2[Cc];

__device__ __forceinline__ void mma_tf32(float* c, const float4& a, const float2& b) {
    asm volatile(
        "mma.sync.aligned.m16n8k8.row.col.f32.tf32.tf32.f32 "
        "{%0,%1,%2,%3}, {%4,%5,%6,%7}, {%8,%9}, {%0,%1,%2,%3};"
        : "+f"(c[0]), "+f"(c[1]), "+f"(c[2]), "+f"(c[3])
        : "r"(__float_as_uint(a.x)), "r"(__float_as_uint(a.y)),
          "r"(__float_as_uint(a.z)), "r"(__float_as_uint(a.w)),
          "r"(__float_as_uint(b.x)), "r"(__float_as_uint(b.y)));
}

__device__ __forceinline__ void mma_f16(float* c, uint32_t a0, uint32_t a1,
                                        uint32_t a2, uint32_t a3,
                                        uint32_t b0, uint32_t b1) {
    asm volatile(
        "mma.sync.aligned.m16n8k16.row.col.f32.f16.f16.f32 "
        "{%0,%1,%2,%3}, {%4,%5,%6,%7}, {%8,%9}, {%0,%1,%2,%3};"
        : "+f"(c[0]), "+f"(c[1]), "+f"(c[2]), "+f"(c[3])
        : "r"(a0), "r"(a1), "r"(a2), "r"(a3), "r"(b0), "r"(b1));
}

__device__ __forceinline__ uint32_t pack2(float x, float y) {
    __half2 h = __floats2half2_rn(x, y);
    return *reinterpret_cast<uint32_t*>(&h);
}

__device__ __forceinline__ float4 half4_to_f4(uint2 hv) {
    float2 f0 = __half22float2(*reinterpret_cast<__half2*>(&hv.x));
    float2 f1 = __half22float2(*reinterpret_cast<__half2*>(&hv.y));
    return make_float4(f0.x, f0.y, f1.x, f1.y);
}

// ---------------------------------------------------------------------------
// Rolls. MODE 0: H,+c  1: W,+c  2: W,-c.
// roll_f2h: fp32 in -> fp16 out (first rolls of x).
// roll_h2h: fp16 in -> fp16 out (mid rolls).
// ---------------------------------------------------------------------------
template <int MODE>
__launch_bounds__(256)
__global__ void roll_f2h(const float* __restrict__ in, __half* __restrict__ out) {
    __shared__ float tile[56 * 128];
    const int tid = threadIdx.x;
    const int b = blockIdx.x / 56;
    const int f = blockIdx.x % 56;
    const size_t base   = (MODE == 0) ? ((size_t)b * Nn + f) * 128
                                      : ((size_t)(b * 56 + f) * 56) * 128;
    const int    stride = (MODE == 0) ? 56 * 128 : 128;

    #pragma unroll
    for (int e = tid; e < 56 * 32; e += 256) {
        int rowi = e >> 5, c4 = e & 31;
        ((float4*)tile)[rowi * 32 + c4] =
            *(const float4*)(in + base + (size_t)rowi * stride + c4 * 4);
    }
    __syncthreads();

    #pragma unroll
    for (int e = tid; e < 56 * 128; e += 256) {
        int pos = e >> 7, c = e & 127;
        int cm = c % 56;
        int src = (MODE == 2) ? pos + cm : pos - cm;
        if (src < 0) src += 56;
        if (src >= 56) src -= 56;
        out[base + (size_t)pos * stride + c] = __float2half(tile[src * 128 + c]);
    }
}

template <int MODE>
__launch_bounds__(256)
__global__ void roll_h2h(const __half* __restrict__ in, __half* __restrict__ out) {
    __shared__ __half tile[56 * 128];
    const int tid = threadIdx.x;
    const int b = blockIdx.x / 56;
    const int f = blockIdx.x % 56;
    const size_t base   = (MODE == 0) ? ((size_t)b * Nn + f) * 128
                                      : ((size_t)(b * 56 + f) * 56) * 128;
    const int    stride = (MODE == 0) ? 56 * 128 : 128;

    #pragma unroll
    for (int e = tid; e < 56 * 16; e += 256) {
        int rowi = e >> 4, cq = e & 15;
        ((uint4*)tile)[rowi * 16 + cq] =
            *(const uint4*)(in + base + (size_t)rowi * stride + cq * 8);
    }
    __syncthreads();

    #pragma unroll
    for (int e = tid; e < 56 * 128; e += 256) {
        int pos = e >> 7, c = e & 127;
        int cm = c % 56;
        int src = (MODE == 2) ? pos + cm : pos - cm;
        if (src < 0) src += 56;
        if (src >= 56) src -= 56;
        out[base + (size_t)pos * stride + c] = tile[src * 128 + c];
    }
}

// ---------------------------------------------------------------------------
// FP16 GEMM (m16n8k16, fp32 accum), R14-validated structure.
// MULTI: 0 single; 1 QKV; 2 DUAL. AMODE: 0 plain; 2 LN fold; 3 bn-fold.
// AH: A (A0/Am) stored fp16 (AMODE 3: only A0 half, A1 float).
// OH: output stored fp16.
// ---------------------------------------------------------------------------
enum { EPI_GELU = 0, EPI_BIAS = 1, EPI_RES = 2 };
constexpr int SM_ALL = 64 * 1024 + 16 * 1024;

template <int K, int EPI, int AMODE, bool BT, int MULTI, bool AH, bool OH>
__launch_bounds__(256, 2)
__global__ void gemm_k(const float* __restrict__ A0, const float* __restrict__ A1,
                       const float* __restrict__ B0, const float* __restrict__ B1,
                       const float* __restrict__ B2,
                       const float* __restrict__ bias0, const float* __restrict__ bias1,
                       const float* __restrict__ bias2,
                       const float* __restrict__ res,
                       const float* __restrict__ p0, const float* __restrict__ p1,
                       const float* __restrict__ p2, const float* __restrict__ p3,
                       float* __restrict__ C0, float* __restrict__ C1,
                       float* __restrict__ C2) {
    extern __shared__ char smemc[];
    uint2* Bs  = (uint2*)smemc;
    char*  Asb = smemc + 65536;

    const float* Am = A0;
    const float* Bm = B0;
    const float* bias = bias0;
    float* Cm = C0;
    if (MULTI == 1) {
        int y = blockIdx.y;
        if (y == 1) { Bm = B1; bias = bias1; Cm = C1; }
        else if (y == 2) { Bm = B2; bias = bias2; Cm = C2; }
    } else if (MULTI == 2) {
        if (blockIdx.y == 1) { Am = A1; Bm = B1; bias = bias1; Cm = C1; }
    }

    const int tid  = threadIdx.x;
    const int lane = tid & 31;
    const int wid  = tid >> 5;
    const int wm   = wid & 3;
    const int wn   = wid >> 2;
    const int row0 = blockIdx.x * 128;
    const int lr   = lane >> 2;
    const int lc   = lane & 3;

    auto loadB = [&]() {
        for (int frag = wid; frag < (K / 16) * 16; frag += 8) {
            int kc = frag >> 4, nt = frag & 15;
            int kk = kc * 16 + lc * 2, n = nt * 8 + lr;
            float v0, v1, v2, v3;
            if (BT) {
                const float* p = Bm + (size_t)n * K + kk;
                v0 = p[0]; v1 = p[1]; v2 = p[8]; v3 = p[9];
            } else {
                v0 = Bm[(size_t)kk * 128 + n];
                v1 = Bm[(size_t)(kk + 1) * 128 + n];
                v2 = Bm[(size_t)(kk + 8) * 128 + n];
                v3 = Bm[(size_t)(kk + 9) * 128 + n];
            }
            Bs[frag * 32 + lane] = make_uint2(pack2(v0, v1), pack2(v2, v3));
        }
    };

    const int arow = tid >> 3;
    const int ac4  = tid & 7;
    float mrow[4], rrow[4];
    if (AMODE == 2) {
        #pragma unroll
        for (int i = 0; i < 4; i++) {
            int gr = row0 + arow + i * 32;
            mrow[i] = p0[gr];
            rrow[i] = p1[gr];
        }
    }

    auto fetch4 = [&](int i, int c) -> float4 {
        int gr = row0 + arow + i * 32;
        float4 v;
        if (AMODE == 0) {
            if (AH)
                v = half4_to_f4(*(const uint2*)((const __half*)Am + (size_t)gr * K + c));
            else
                v = *(const float4*)(Am + (size_t)gr * K + c);
        } else {
            if (c < 128) {
                if (AH && AMODE == 3)
                    v = half4_to_f4(*(const uint2*)((const __half*)A0 + (size_t)gr * 128 + c));
                else
                    v = *(const float4*)(A0 + (size_t)gr * 128 + c);
            } else {
                v = *(const float4*)(A1 + (size_t)gr * 128 + (c - 128));
            }
            if (AMODE == 2) {
                float4 g = *(const float4*)(p2 + c);
                float4 bb = *(const float4*)(p3 + c);
                float mn = mrow[i], rs = rrow[i];
                v.x = (v.x - mn) * rs * g.x + bb.x;
                v.y = (v.y - mn) * rs * g.y + bb.y;
                v.z = (v.z - mn) * rs * g.z + bb.z;
                v.w = (v.w - mn) * rs * g.w + bb.w;
            } else if (AMODE == 3) {
                if (c >= 128) {
                    float4 sa = *(const float4*)(p0 + c - 128);
                    float4 ha = *(const float4*)(p1 + c - 128);
                    float4 sb = *(const float4*)(p2 + c - 128);
                    float4 hb = *(const float4*)(p3 + c - 128);
                    v.x = fmaxf(v.x * sa.x + ha.x, 0.f) * sb.x + hb.x;
                    v.y = fmaxf(v.y * sa.y + ha.y, 0.f) * sb.y + hb.y;
                    v.z = fmaxf(v.z * sa.z + ha.z, 0.f) * sb.z + hb.z;
                    v.w = fmaxf(v.w * sa.w + ha.w, 0.f) * sb.w + hb.w;
                }
            }
        }
        return v;
    };

    float4 pa[2][4];
    auto gather = [&](int kc, int set) {
        int c = kc + ac4 * 4;
        #pragma unroll
        for (int i = 0; i < 4; i++) pa[set][i] = fetch4(i, c);
    };

    loadB();
    gather(0, 0);
    gather(32, 1);

    float acc[2][8][4] = {};
    constexpr int NS = K / 32;

    #pragma unroll
    for (int s = 0; s < NS; s++) {
        const int set = s & 1;
        char* Ab = Asb + set * 8192;
        #pragma unroll
        for (int i = 0; i < 4; i++) {
            int row = arow + i * 32;
            uint2 hv = make_uint2(pack2(pa[set][i].x, pa[set][i].y),
                                  pack2(pa[set][i].z, pa[set][i].w));
            *(uint2*)(Ab + row * 64 + 8 * (ac4 ^ (row & 7))) = hv;
        }
        __syncthreads();
        if (s + 2 < NS) gather((s + 2) * 32, set);
        #pragma unroll
        for (int kc = 0; kc < 2; kc++) {
            const int g   = kc * 4 + (lc >> 1);
            const int g2  = g + 2;
            const int off = (lc & 1) * 4;
            uint32_t af[2][4];
            #pragma unroll
            for (int mt2 = 0; mt2 < 2; mt2++) {
                int r = wm * 32 + mt2 * 16 + lr;
                int q = r & 7;
                const char* r1p = Ab + r * 64 + off;
                const char* r2p = Ab + (r + 8) * 64 + off;
                af[mt2][0] = *(const uint32_t*)(r1p + 8 * (g  ^ q));
                af[mt2][1] = *(const uint32_t*)(r2p + 8 * (g  ^ q));
                af[mt2][2] = *(const uint32_t*)(r1p + 8 * (g2 ^ q));
                af[mt2][3] = *(const uint32_t*)(r2p + 8 * (g2 ^ q));
            }
            const int cb = (s * 2 + kc) * 16 + wn * 8;
            #pragma unroll
            for (int u = 0; u < 8; u++) {
                uint2 b = Bs[(cb + u) * 32 + lane];
                mma_f16(acc[0][u], af[0][0], af[0][1], af[0][2], af[0][3], b.x, b.y);
                mma_f16(acc[1][u], af[1][0], af[1][1], af[1][2], af[1][3], b.x, b.y);
            }
        }
    }

    const int ec = lc * 2;
    #pragma unroll
    for (int t = 0; t < 2; t++) {
        int m0 = row0 + wm * 32 + t * 16 + lr;
        #pragma unroll
        for (int u = 0; u < 8; u++) {
            int n = wn * 64 + u * 8 + ec;
            float b0 = bias[n], b1 = bias[n + 1];
            float v0 = acc[t][u][0] + b0;
            float v1 = acc[t][u][1] + b1;
            float v2 = acc[t][u][2] + b0;
            float v3 = acc[t][u][3] + b1;
            if (EPI == EPI_GELU) {
                v0 = 0.5f * v0 * (1.0f + erff(v0 * 0.70710678f));
                v1 = 0.5f * v1 * (1.0f + erff(v1 * 0.70710678f));
                v2 = 0.5f * v2 * (1.0f + erff(v2 * 0.70710678f));
                v3 = 0.5f * v3 * (1.0f + erff(v3 * 0.70710678f));
            } else if (EPI == EPI_RES) {
                float2 r0 = *(const float2*)(res + (size_t)m0 * 128 + n);
                float2 rr = *(const float2*)(res + (size_t)(m0 + 8) * 128 + n);
                v0 += r0.x; v1 += r0.y; v2 += rr.x; v3 += rr.y;
            }
            if (OH) {
                __half* Ch = (__half*)Cm;
                *(uint32_t*)(Ch + (size_t)m0 * 128 + n)       = pack2(v0, v1);
                *(uint32_t*)(Ch + (size_t)(m0 + 8) * 128 + n) = pack2(v2, v3);
            } else {
                *(float2*)(Cm + (size_t)m0 * 128 + n)       = make_float2(v0, v1);
                *(float2*)(Cm + (size_t)(m0 + 8) * 128 + n) = make_float2(v2, v3);
            }
        }
    }
}

// ---------------------------------------------------------------------------
// LayerNorm stats only
// ---------------------------------------------------------------------------
__global__ void ln_stats_k(const float* __restrict__ x1a, const float* __restrict__ x2a,
                           float* __restrict__ mean, float* __restrict__ rstd) {
    int warp = (blockIdx.x * blockDim.x + threadIdx.x) >> 5;
    int lane = threadIdx.x & 31;
    if (warp >= Mm) return;
    float s = 0.f, sq = 0.f;
    #pragma unroll
    for (int kq = 0; kq < 4; kq++) {
        float a = x1a[(size_t)warp * 128 + lane + 32 * kq];
        float b = x2a[(size_t)warp * 128 + lane + 32 * kq];
        s += a + b; sq += a * a + b * b;
    }
    #pragma unroll
    for (int o = 16; o > 0; o >>= 1) {
        s  += __shfl_xor_sync(0xffffffffu, s, o);
        sq += __shfl_xor_sync(0xffffffffu, sq, o);
    }
    if (lane == 0) {
        float mu = s * (1.f / 256.f);
        float var = sq * (1.f / 256.f) - mu * mu;
        mean[warp] = mu;
        rstd[warp] = rsqrtf(var + 1e-5f);
    }
}

// ---------------------------------------------------------------------------
// Window attention: fp16 inputs loaded directly into fp16 smem (R15 layout).
// ---------------------------------------------------------------------------
constexpr int QH = 136;
constexpr int PH = 72;
constexpr int VH = 136;
constexpr int ATTN_SMEM = (2 * 64 * QH + 64 * VH) * 2;

__launch_bounds__(256)
__global__ void attn_k(const __half* __restrict__ q, const __half* __restrict__ k,
                       const __half* __restrict__ v, float* __restrict__ out) {
    extern __shared__ __half smh[];
    __half* Qs = smh;
    __half* Ks = Qs + 64 * QH;
    __half* Vs = Ks + 64 * QH;
    __half* Ps = Qs;

    const int widx = blockIdx.x;
    const int b = widx >> 6, wh = (widx >> 3) & 7, ww = widx & 7;
    const int tid  = threadIdx.x;
    const int lane = tid & 31, w = tid >> 5;
    const int wm = w & 3, wn = w >> 2;
    const int lr = lane >> 2, lc = lane & 3;

    auto grow = [&](int i) -> size_t {
        return ((size_t)(b * Nn + (wh * 7 + i / 7) * 56 + ww * 7 + (i % 7))) * 128;
    };

    for (int e = tid; e < 49 * 32; e += 256) {
        int i = e >> 5, c4 = (e & 31) * 4;
        size_t g = grow(i) + c4;
        *(uint2*)(Qs + i * QH + c4) = *(const uint2*)(q + g);
        *(uint2*)(Ks + i * QH + c4) = *(const uint2*)(k + g);
        *(uint2*)(Vs + i * VH + c4) = *(const uint2*)(v + g);
    }
    for (int e = tid; e < 15 * VH / 2; e += 256)
        ((uint32_t*)(Vs + 49 * VH))[e] = 0u;
    __syncthreads();

    float acc[4][4] = {};
    #pragma unroll
    for (int ks = 0; ks < 8; ks++) {
        int r = wm * 16 + lr, c = ks * 16 + lc * 2;
        uint32_t a0 = *(const uint32_t*)(Qs + r * QH + c);
        uint32_t a1 = *(const uint32_t*)(Qs + (r + 8) * QH + c);
        uint32_t a2 = *(const uint32_t*)(Qs + r * QH + c + 8);
        uint32_t a3 = *(const uint32_t*)(Qs + (r + 8) * QH + c + 8);
        #pragma unroll
        for (int u = 0; u < 4; u++) {
            int n = wn * 32 + u * 8 + lr;
            uint32_t b0 = *(const uint32_t*)(Ks + n * QH + c);
            uint32_t b1 = *(const uint32_t*)(Ks + n * QH + c + 8);
            mma_f16(acc[u], a0, a1, a2, a3, b0, b1);
        }
    }
    __syncthreads();
    #pragma unroll
    for (int u = 0; u < 4; u++) {
        int r = wm * 16 + lr, n = wn * 32 + u * 8 + lc * 2;
        *(uint32_t*)(Ps + r * PH + n)       = pack2(acc[u][0], acc[u][1]);
        *(uint32_t*)(Ps + (r + 8) * PH + n) = pack2(acc[u][2], acc[u][3]);
    }
    __syncthreads();

    if (tid < 49) {
        const float scale = 0.08838834764831845f;
        __half* r = Ps + tid * PH;
        float mx = __half2float(r[0]);
        #pragma unroll 7
        for (int j = 1; j < 49; j++) mx = fmaxf(mx, __half2float(r[j]));
        float s = 0.f;
        #pragma unroll 7
        for (int j = 0; j < 49; j++) {
            float e = expf((__half2float(r[j]) - mx) * scale);
            r[j] = __float2half(e);
            s += e;
        }
        float inv = 1.f / s;
        #pragma unroll 7
        for (int j = 0; j < 49; j++)
            r[j] = __float2half(__half2float(r[j]) * inv);
        #pragma unroll
        for (int j = 49; j < 64; j++) r[j] = __float2half(0.f);
    }
    __syncthreads();

    float o[8][4] = {};
    #pragma unroll
    for (int k8 = 0; k8 < 8; k8++) {
        int r = wm * 16 + lr, c = k8 * 8 + lc;
        float4 a = make_float4(__half2float(Ps[r * PH + c]),
                               __half2float(Ps[(r + 8) * PH + c]),
                               __half2float(Ps[r * PH + c + 4]),
                               __half2float(Ps[(r + 8) * PH + c + 4]));
        #pragma unroll
        for (int u = 0; u < 8; u++) {
            int n = wn * 64 + u * 8 + lr;
            float2 bf = make_float2(__half2float(Vs[c * VH + n]),
                                    __half2float(Vs[(c + 4) * VH + n]));
            mma_tf32(o[u], a, bf);
        }
    }
    int r0 = wm * 16 + lr;
    #pragma unroll
    for (int u = 0; u < 8; u++) {
        int n = wn * 64 + u * 8 + lc * 2;
        if (r0 < 49)     *(float2*)(out + grow(r0) + n)     = make_float2(o[u][0], o[u][1]);
        if (r0 + 8 < 49) *(float2*)(out + grow(r0 + 8) + n) = make_float2(o[u][2], o[u][3]);
    }
}

// ---------------------------------------------------------------------------
// BatchNorm pieces
// ---------------------------------------------------------------------------
__global__ void bn_stats_k(const float* __restrict__ x, float* __restrict__ part) {
    int c = threadIdx.x & 127;
    int half = threadIdx.x >> 7;
    float s = 0.f, sq = 0.f;
    int rbeg = blockIdx.x * 128 + half;
    int rend = blockIdx.x * 128 + 128;
    for (int r = rbeg; r < rend; r += 2) {
        float vv = x[(size_t)r * 128 + c];
        s += vv; sq += vv * vv;
    }
    __shared__ float sh[512];
    sh[threadIdx.x] = s;
    sh[256 + threadIdx.x] = sq;
    __syncthreads();
    if (half == 0) {
        part[blockIdx.x * 256 + c]       = sh[c] + sh[128 + c];
        part[blockIdx.x * 256 + 128 + c] = sh[256 + c] + sh[256 + 128 + c];
    }
}

__global__ void bn2_stats_k(const float* __restrict__ x,
                            const float* __restrict__ s1, const float* __restrict__ h1,
                            float* __restrict__ part) {
    int c = threadIdx.x & 127;
    int half = threadIdx.x >> 7;
    float sc = s1[c], sh_ = h1[c];
    float s = 0.f, sq = 0.f;
    int rbeg = blockIdx.x * 128 + half;
    int rend = blockIdx.x * 128 + 128;
    for (int r = rbeg; r < rend; r += 2) {
        float vv = fmaxf(x[(size_t)r * 128 + c] * sc + sh_, 0.f);
        s += vv; sq += vv * vv;
    }
    __shared__ float shm[512];
    shm[threadIdx.x] = s;
    shm[256 + threadIdx.x] = sq;
    __syncthreads();
    if (half == 0) {
        part[blockIdx.x * 256 + c]       = shm[c] + shm[128 + c];
        part[blockIdx.x * 256 + 128 + c] = shm[256 + c] + shm[256 + 128 + c];
    }
}

__global__ void bn_reduce_k(const float* __restrict__ part, const float* __restrict__ g,
                            const float* __restrict__ beta, float* __restrict__ scale,
                            float* __restrict__ shift) {
    int c = threadIdx.x;
    float s = 0.f, sq = 0.f;
    for (int i = 0; i < 784; i++) {
        s  += part[i * 256 + c];
        sq += part[i * 256 + 128 + c];
    }
    float mean = s / (float)Mm;
    float var  = sq / (float)Mm - mean * mean;
    float sc_  = g[c] * rsqrtf(var + 1e-5f);
    scale[c] = sc_;
    shift[c] = beta[c] - mean * sc_;
}

// ---------------------------------------------------------------------------
// Host launch
// ---------------------------------------------------------------------------
static float* symaddr(const void* devsym) {
    void* p = nullptr;
    cudaGetSymbolAddress(&p, devsym);
    return (float*)p;
}

extern "C" void kernel_launch(void* const* d_in, const int* in_sizes, int n_in,
                              void* d_out, int out_size) {
    const float* x     = (const float*)d_in[0];
    const float* fc1_w = (const float*)d_in[1];
    const float* fc1_b = (const float*)d_in[2];
    const float* fc2_w = (const float*)d_in[3];
    const float* fc2_b = (const float*)d_in[4];
    const float* fc3_w = (const float*)d_in[5];
    const float* fc3_b = (const float*)d_in[6];
    const float* fc4_w = (const float*)d_in[7];
    const float* fc4_b = (const float*)d_in[8];
    const float* fc5_w = (const float*)d_in[9];
    const float* fc5_b = (const float*)d_in[10];
    const float* fc6_w = (const float*)d_in[11];
    const float* fc6_b = (const float*)d_in[12];
    const float* ln_w  = (const float*)d_in[13];
    const float* ln_b  = (const float*)d_in[14];
    const float* q_w   = (const float*)d_in[15];
    const float* q_b   = (const float*)d_in[16];
    const float* k_w   = (const float*)d_in[17];
    const float* k_b   = (const float*)d_in[18];
    const float* v_w   = (const float*)d_in[19];
    const float* v_b   = (const float*)d_in[20];
    const float* bn1_g = (const float*)d_in[21];
    const float* bn1_b = (const float*)d_in[22];
    const float* bn2_g = (const float*)d_in[23];
    const float* bn2_b = (const float*)d_in[24];

    float* t0   = symaddr(g_t0);
    float* t1   = symaddr(g_t1);
    float* x1a  = symaddr(g_x1a);
    float* x2a  = symaddr(g_x2a);
    float* qb   = symaddr(g_q);
    float* kb   = symaddr(g_k);
    float* vb   = symaddr(g_v);
    float* att  = symaddr(g_att);
    float* stat = symaddr(g_stats);
    float* mean = stat;
    float* rstd = stat + Mm;
    float* part = symaddr(g_part);
    float* s1   = symaddr(g_s1);
    float* h1   = symaddr(g_h1);
    float* s2   = symaddr(g_s2);
    float* h2   = symaddr(g_h2);

    __half* t0h = (__half*)t0;
    __half* t1h = (__half*)t1;
    __half* qbh = (__half*)qb;
    __half* kbh = (__half*)kb;
    __half* vbh = (__half*)vb;

    const int gridR = Bb * 56;
    const int gridG = Mm / 128;          // 784

    auto setsm = [](const void* f) {
        cudaFuncSetAttribute(f, cudaFuncAttributeMaxDynamicSharedMemorySize, SM_ALL);
    };
    setsm((const void*)gemm_k<128, EPI_GELU, 0, false, 2, true,  true >);
    setsm((const void*)gemm_k<128, EPI_RES,  0, false, 2, true,  false>);
    setsm((const void*)gemm_k<128, EPI_BIAS, 0, true,  1, false, true >);
    setsm((const void*)gemm_k<256, EPI_RES,  2, false, 0, false, true >);
    setsm((const void*)gemm_k<256, EPI_BIAS, 3, false, 0, true,  false>);
    cudaFuncSetAttribute(attn_k, cudaFuncAttributeMaxDynamicSharedMemorySize, ATTN_SMEM);

    // Rolls of x (fp32 -> fp16): t0h = H,+c ; qbh = W,-c
    roll_f2h<0><<<gridR, 256>>>(x, t0h);
    roll_f2h<2><<<gridR, 256>>>(x, qbh);

    // fc1 || fc3 (DUAL, half A, half out): -> t1h, kbh
    gemm_k<128, EPI_GELU, 0, false, 2, true, true><<<dim3(gridG, 2), 256, SM_ALL>>>(
        (const float*)t0h, (const float*)qbh, fc1_w, fc3_w, nullptr,
        fc1_b, fc3_b, nullptr, nullptr,
        nullptr, nullptr, nullptr, nullptr, (float*)t1h, (float*)kbh, nullptr);

    // mid rolls (fp16 -> fp16)
    roll_h2h<1><<<gridR, 256>>>(t1h, t0h);
    roll_h2h<0><<<gridR, 256>>>(kbh, qbh);

    // fc2 || fc4 (DUAL, half A, fp32 out) + residual x -> x1a, x2a
    gemm_k<128, EPI_RES, 0, false, 2, true, false><<<dim3(gridG, 2), 256, SM_ALL>>>(
        (const float*)t0h, (const float*)qbh, fc2_w, fc4_w, nullptr,
        fc2_b, fc4_b, nullptr, x,
        nullptr, nullptr, nullptr, nullptr, x1a, x2a, nullptr);

    // LN stats + fc5 (LN folded, fp32 A, half out) + residual -> t0h
    ln_stats_k<<<Mm / 8, 256>>>(x1a, x2a, mean, rstd);
    gemm_k<256, EPI_RES, 2, false, 0, false, true><<<gridG, 256, SM_ALL>>>(
        x1a, x2a, fc5_w, nullptr, nullptr, fc5_b, nullptr, nullptr, x,
        mean, rstd, ln_w, ln_b, (float*)t0h, nullptr, nullptr);

    // q/k/v (fp32 A = x, half outs)
    gemm_k<128, EPI_BIAS, 0, true, 1, false, true><<<dim3(gridG, 3), 256, SM_ALL>>>(
        x, nullptr, q_w, k_w, v_w, q_b, k_b, v_b, nullptr,
        nullptr, nullptr, nullptr, nullptr, (float*)qbh, (float*)kbh, (float*)vbh);

    // Window attention (fp16 in, fp32 out)
    attn_k<<<2048, 256, ATTN_SMEM>>>(qbh, kbh, vbh, att);

    // BN chain (read-only on att)
    bn_stats_k<<<784, 256>>>(att, part);
    bn_reduce_k<<<1, 128>>>(part, bn1_g, bn1_b, s1, h1);
    bn2_stats_k<<<784, 256>>>(att, s1, h1, part);
    bn_reduce_k<<<1, 128>>>(part, bn2_g, bn2_b, s2, h2);

    // Final: out = [x1(half) | relu(bn1(att))*bn2] @ fc6 + b
    gemm_k<256, EPI_BIAS, 3, false, 0, true, false><<<gridG, 256, SM_ALL>>>(
        (const float*)t0h, att, fc6_w, nullptr, nullptr, fc6_b, nullptr, nullptr, nullptr,
        s1, h1, s2, h2, (float*)d_out, nullptr, nullptr);
}